// round 12
// baseline (speedup 1.0000x reference)
#include <cuda_runtime.h>
#include <math.h>
#include <stddef.h>
#include <stdint.h>

// Problem constants
#define BB 2
#define LL 2048
#define DD 1024
#define HH 16
#define DHD 64
#define RR 32
#define NROWS (BB*LL)          // 4096
#define LORA_SCALE 2.0f
#define ATTN_SCALE 0.125f      // 1/sqrt(64)

// -------------------- scratch (static device memory, allowed) --------------------
__device__ float g_h[NROWS * DD];          // tf32-rounded LN(x)
__device__ float g_weff[3 * DD * DD];      // tf32-rounded qkv weight + lora
__device__ float g_qkv[NROWS * 3 * DD];
__device__ float g_q[BB * HH * LL * DHD];  // [B,H,L,DH]
__device__ float g_k[BB * HH * LL * DHD];
__device__ float g_v[BB * HH * LL * DHD];
__device__ float g_ctx[NROWS * DD];        // tf32-rounded attention output
__device__ float g_rcos[LL * 32];
__device__ float g_rsin[LL * 32];
__device__ float g_wout_r[DD * DD];        // tf32-rounded w_out

// -------------------- helpers --------------------
__device__ __forceinline__ uint32_t f2tf32(float f) {
    uint32_t r;
    asm("cvt.rna.tf32.f32 %0, %1;" : "=r"(r) : "f"(f));
    return r;
}
__device__ __forceinline__ float rnd_tf32(float f) {
    return __uint_as_float(f2tf32(f));
}

__device__ __forceinline__ void mma_tf32(float* c, const uint32_t* a, const uint32_t* b) {
    asm volatile(
        "mma.sync.aligned.m16n8k8.row.col.f32.tf32.tf32.f32 "
        "{%0,%1,%2,%3}, {%4,%5,%6,%7}, {%8,%9}, {%0,%1,%2,%3};\n"
        : "+f"(c[0]), "+f"(c[1]), "+f"(c[2]), "+f"(c[3])
        : "r"(a[0]), "r"(a[1]), "r"(a[2]), "r"(a[3]), "r"(b[0]), "r"(b[1]));
}

__device__ __forceinline__ void cp_async16(uint32_t saddr, const void* gptr) {
    asm volatile("cp.async.ca.shared.global [%0], [%1], 16;\n" :: "r"(saddr), "l"(gptr));
}
__device__ __forceinline__ void cp_commit() {
    asm volatile("cp.async.commit_group;\n");
}
template<int N>
__device__ __forceinline__ void cp_wait() {
    asm volatile("cp.async.wait_group %0;\n" :: "n"(N));
}

__device__ __forceinline__ float4 block_reduce4(float4 v, float4* buf) {
#pragma unroll
    for (int o = 16; o; o >>= 1) {
        v.x += __shfl_xor_sync(0xffffffffu, v.x, o);
        v.y += __shfl_xor_sync(0xffffffffu, v.y, o);
        v.z += __shfl_xor_sync(0xffffffffu, v.z, o);
        v.w += __shfl_xor_sync(0xffffffffu, v.w, o);
    }
    int w = threadIdx.x >> 5, lane = threadIdx.x & 31;
    if (lane == 0) buf[w] = v;
    __syncthreads();
    if (w == 0) {
        v = (lane < 8) ? buf[lane] : make_float4(0.f, 0.f, 0.f, 0.f);
#pragma unroll
        for (int o = 4; o; o >>= 1) {
            v.x += __shfl_xor_sync(0xffffffffu, v.x, o);
            v.y += __shfl_xor_sync(0xffffffffu, v.y, o);
            v.z += __shfl_xor_sync(0xffffffffu, v.z, o);
            v.w += __shfl_xor_sync(0xffffffffu, v.w, o);
        }
        if (lane == 0) buf[0] = v;
    }
    __syncthreads();
    return buf[0];
}

// -------------------- 0) RoPE table --------------------
__global__ void rope_table_kernel(float* __restrict__ rc, float* __restrict__ rs) {
    int i = blockIdx.x * blockDim.x + threadIdx.x;
    if (i >= LL * 32) return;
    int l = i >> 5, jj = i & 31;
    double invf = exp(-0.28782313662425575 * (double)jj);
    double ang = (double)l * invf;
    double sd, cd;
    sincos(ang, &sd, &cd);
    rc[i] = (float)cd;
    rs[i] = (float)sd;
}

// -------------------- 1) input LayerNorm (pre-rounded output) --------------------
__global__ void ln_kernel(const float* __restrict__ x, const float* __restrict__ w,
                          const float* __restrict__ b, float* __restrict__ out) {
    __shared__ float4 buf[8];
    int n = blockIdx.x;
    int tid = threadIdx.x;
    const float4* xr = reinterpret_cast<const float4*>(x + (size_t)n * DD);
    float4 xv = xr[tid];
    float4 sums = make_float4(xv.x + xv.y + xv.z + xv.w,
                              xv.x * xv.x + xv.y * xv.y + xv.z * xv.z + xv.w * xv.w,
                              0.f, 0.f);
    float4 r = block_reduce4(sums, buf);
    float mu = r.x * (1.f / DD);
    float var = r.y * (1.f / DD) - mu * mu;
    float inv = rsqrtf(var + 1e-5f);
    float4 wv = reinterpret_cast<const float4*>(w)[tid];
    float4 bv = reinterpret_cast<const float4*>(b)[tid];
    float4 o;
    o.x = rnd_tf32((xv.x - mu) * inv * wv.x + bv.x);
    o.y = rnd_tf32((xv.y - mu) * inv * wv.y + bv.y);
    o.z = rnd_tf32((xv.z - mu) * inv * wv.z + bv.z);
    o.w = rnd_tf32((xv.w - mu) * inv * wv.w + bv.w);
    reinterpret_cast<float4*>(out + (size_t)n * DD)[tid] = o;
}

// -------------------- 2) fold LoRA into QKV weight + round w_out (fused) ----------
__global__ void weff_kernel(const float* __restrict__ wqkv,
                            const float* __restrict__ qa, const float* __restrict__ qb,
                            const float* __restrict__ va, const float* __restrict__ vb,
                            const float* __restrict__ wout, float* __restrict__ woutr,
                            float* __restrict__ weff) {
    int idx = blockIdx.x * blockDim.x + threadIdx.x;
    if (idx >= 4 * DD * DD) return;
    if (idx >= 3 * DD * DD) {                 // tail: round w_out
        int i = idx - 3 * DD * DD;
        woutr[i] = rnd_tf32(wout[i]);
        return;
    }
    int e = idx >> 10, d = idx & 1023;
    float w = wqkv[idx];
    if (e < DD) {
        float s = 0.f;
#pragma unroll
        for (int r = 0; r < RR; ++r) s += qb[e * RR + r] * qa[r * DD + d];
        w += LORA_SCALE * s;
    } else if (e >= 2 * DD) {
        int eb = e - 2 * DD;
        float s = 0.f;
#pragma unroll
        for (int r = 0; r < RR; ++r) s += vb[eb * RR + r] * va[r * DD + d];
        w += LORA_SCALE * s;
    }
    weff[idx] = rnd_tf32(w);
}

// -------------------- 3/6) TF32 GEMM: 4 warps, 64x64 warp tile, raw-bit frags ------
#define BM 128
#define BN 128
#define BK 16
#define SKW (BK + 8)   // 24
#define GSTG 3
#define SMEM_GEMM (GSTG * 2 * BM * SKW * 4)   // 73728 bytes

#define AS(s, r, c) sm_a[((s) * BM + (r)) * SKW + (c)]
#define WS(s, r, c) sm_w[((s) * BN + (r)) * SKW + (c)]

__global__ void __launch_bounds__(128, 3) gemm_tf32(const float* __restrict__ A,
                                                    const float* __restrict__ W,
                                                    float* __restrict__ C,
                                                    int M, int N, int K) {
    extern __shared__ uint32_t sm[];
    uint32_t* sm_a = sm;
    uint32_t* sm_w = sm + GSTG * BM * SKW;

    const int tid = threadIdx.x;
    const int lane = tid & 31;
    const int wid = tid >> 5;               // 0..3
    const int g = lane >> 2, tg = lane & 3;
    const int wm = wid >> 1, wn = wid & 1;  // 2 x 2 warp grid, 64x64 warp tile
    const int bm = blockIdx.y * BM, bn = blockIdx.x * BN;

    int row_[4], kc_[4];
#pragma unroll
    for (int l = 0; l < 4; ++l) {
        int idx = tid + l * 128;
        row_[l] = idx >> 2;
        kc_[l] = (idx & 3) << 2;
    }

    const float* gA = A + (size_t)bm * K;
    const float* gW = W + (size_t)bn * K;

    auto issue = [&](int s, int t) {
#pragma unroll
        for (int l = 0; l < 4; ++l) {
            uint32_t sa = (uint32_t)__cvta_generic_to_shared(&AS(s, row_[l], kc_[l]));
            cp_async16(sa, gA + (size_t)row_[l] * K + t * BK + kc_[l]);
            uint32_t sw = (uint32_t)__cvta_generic_to_shared(&WS(s, row_[l], kc_[l]));
            cp_async16(sw, gW + (size_t)row_[l] * K + t * BK + kc_[l]);
        }
        cp_commit();
    };

    const int nk = K / BK;
    issue(0, 0);
    issue(1, 1);

    float c[4][8][4] = {};

    for (int t = 0; t < nk; ++t) {
        if (t + 2 < nk) cp_wait<1>(); else cp_wait<0>();
        __syncthreads();
        if (t + 2 < nk) issue((t + 2) % GSTG, t + 2);

        const int buf = t % GSTG;
#pragma unroll
        for (int ks = 0; ks < BK; ks += 8) {
            uint32_t af[4][4], bf[8][2];
#pragma unroll
            for (int mt = 0; mt < 4; ++mt) {
                int m = wm * 64 + mt * 16;
                uint2 a0 = *reinterpret_cast<const uint2*>(&AS(buf, m + g,     ks + 2 * tg));
                uint2 a1 = *reinterpret_cast<const uint2*>(&AS(buf, m + g + 8, ks + 2 * tg));
                af[mt][0] = a0.x; af[mt][2] = a0.y;
                af[mt][1] = a1.x; af[mt][3] = a1.y;
            }
#pragma unroll
            for (int nt = 0; nt < 8; ++nt) {
                int n = wn * 64 + nt * 8;
                uint2 b0 = *reinterpret_cast<const uint2*>(&WS(buf, n + g, ks + 2 * tg));
                bf[nt][0] = b0.x; bf[nt][1] = b0.y;
            }
#pragma unroll
            for (int mt = 0; mt < 4; ++mt)
#pragma unroll
                for (int nt = 0; nt < 8; ++nt)
                    mma_tf32(c[mt][nt], af[mt], bf[nt]);
        }
    }

#pragma unroll
    for (int mt = 0; mt < 4; ++mt) {
        int row0 = bm + wm * 64 + mt * 16 + g;
#pragma unroll
        for (int nt = 0; nt < 8; ++nt) {
            int col = bn + wn * 64 + nt * 8 + 2 * tg;
            *reinterpret_cast<float2*>(C + (size_t)row0 * N + col) =
                make_float2(c[mt][nt][0], c[mt][nt][1]);
            *reinterpret_cast<float2*>(C + (size_t)(row0 + 8) * N + col) =
                make_float2(c[mt][nt][2], c[mt][nt][3]);
        }
    }
}

// -------------------- 4) q/k LN + RoPE + head transpose --------------------
__global__ void transform_kernel(const float* __restrict__ qkv,
                                 const float* __restrict__ qw, const float* __restrict__ kw,
                                 const float* __restrict__ rcos, const float* __restrict__ rsin,
                                 float* __restrict__ gq, float* __restrict__ gk,
                                 float* __restrict__ gv) {
    __shared__ float sq[DD];
    __shared__ float sk[DD];
    __shared__ float4 buf[8];
    int n = blockIdx.x;
    int b = n >> 11, l = n & 2047;
    int tid = threadIdx.x;
    const float* row = qkv + (size_t)n * (3 * DD);
    float4 qv = reinterpret_cast<const float4*>(row)[tid];
    float4 kv = reinterpret_cast<const float4*>(row + DD)[tid];
    float4 vv = reinterpret_cast<const float4*>(row + 2 * DD)[tid];

    {
        int d = tid * 4;
        int h = d >> 6, j = d & 63;
        float* dst = gv + ((((size_t)b * HH + h) * LL + l) * DHD + j);
        *reinterpret_cast<float4*>(dst) = vv;
    }

    float4 sums = make_float4(qv.x + qv.y + qv.z + qv.w,
                              qv.x * qv.x + qv.y * qv.y + qv.z * qv.z + qv.w * qv.w,
                              kv.x + kv.y + kv.z + kv.w,
                              kv.x * kv.x + kv.y * kv.y + kv.z * kv.z + kv.w * kv.w);
    float4 r = block_reduce4(sums, buf);
    float muq = r.x * (1.f / DD), ivq = rsqrtf(r.y * (1.f / DD) - muq * muq + 1e-5f);
    float muk = r.z * (1.f / DD), ivk = rsqrtf(r.w * (1.f / DD) - muk * muk + 1e-5f);
    float4 qwv = reinterpret_cast<const float4*>(qw)[tid];
    float4 kwv = reinterpret_cast<const float4*>(kw)[tid];
    int d0 = tid * 4;
    sq[d0 + 0] = (qv.x - muq) * ivq * qwv.x;
    sq[d0 + 1] = (qv.y - muq) * ivq * qwv.y;
    sq[d0 + 2] = (qv.z - muq) * ivq * qwv.z;
    sq[d0 + 3] = (qv.w - muq) * ivq * qwv.w;
    sk[d0 + 0] = (kv.x - muk) * ivk * kwv.x;
    sk[d0 + 1] = (kv.y - muk) * ivk * kwv.y;
    sk[d0 + 2] = (kv.z - muk) * ivk * kwv.z;
    sk[d0 + 3] = (kv.w - muk) * ivk * kwv.w;
    __syncthreads();

    float oq[4], ok[4];
#pragma unroll
    for (int c = 0; c < 4; ++c) {
        int d = d0 + c;
        int j = d & 63;
        int jj = j & 31;
        float cs = rcos[l * 32 + jj];
        float sn = rsin[l * 32 + jj];
        if (j < 32) {
            oq[c] = sq[d] * cs - sq[d + 32] * sn;
            ok[c] = sk[d] * cs - sk[d + 32] * sn;
        } else {
            oq[c] = sq[d] * cs + sq[d - 32] * sn;
            ok[c] = sk[d] * cs + sk[d - 32] * sn;
        }
    }
    int h = d0 >> 6, j = d0 & 63;
    size_t base = (((size_t)b * HH + h) * LL + l) * DHD + j;
    *reinterpret_cast<float4*>(gq + base) = make_float4(oq[0], oq[1], oq[2], oq[3]);
    *reinterpret_cast<float4*>(gk + base) = make_float4(ok[0], ok[1], ok[2], ok[3]);
}

// -------------------- 5) tensor-core flash attention (3xTF32, R7 + occ=4) ----------
#define QT 64
#define KT2 32
#define KPAD 72
#define VPAD 40

__device__ __forceinline__ int perm_k(int d) {
    return 8 * (d >> 3) + 2 * (d & 3) + ((d >> 2) & 1);
}

__global__ void __launch_bounds__(128, 4) attn_tc_kernel(const float* __restrict__ gq,
                                                         const float* __restrict__ gk,
                                                         const float* __restrict__ gv,
                                                         const int* __restrict__ seq_id,
                                                         float* __restrict__ ctx) {
    __shared__ __align__(16) uint32_t Khi[KT2][KPAD];
    __shared__ __align__(16) uint32_t Klo[KT2][KPAD];
    __shared__ __align__(16) uint32_t Vth[DHD][VPAD];
    __shared__ __align__(16) uint32_t Vtl[DHD][VPAD];
    __shared__ int sk_s[KT2];

    const int q0 = blockIdx.x * QT;
    const int h = blockIdx.y;
    const int b = blockIdx.z;
    const float* qbase = gq + (((size_t)b * HH + h) * LL) * DHD;
    const float* kbase = gk + (((size_t)b * HH + h) * LL) * DHD;
    const float* vbase = gv + (((size_t)b * HH + h) * LL) * DHD;
    const int* sid = seq_id + (size_t)b * LL;

    const int tid = threadIdx.x;
    const int lane = tid & 31;
    const int wid = tid >> 5;
    const int g = lane >> 2, tg = lane & 3;
    const int wrow = wid * 16;

    uint32_t qhi[8][4], qlo[8][4];
    {
        const float* r0 = qbase + (size_t)(q0 + wrow + g) * DHD;
        const float* r1 = qbase + (size_t)(q0 + wrow + g + 8) * DHD;
#pragma unroll
        for (int ks = 0; ks < 8; ++ks) {
            float f[4];
            f[0] = r0[ks * 8 + tg]     * ATTN_SCALE;
            f[1] = r1[ks * 8 + tg]     * ATTN_SCALE;
            f[2] = r0[ks * 8 + tg + 4] * ATTN_SCALE;
            f[3] = r1[ks * 8 + tg + 4] * ATTN_SCALE;
#pragma unroll
            for (int j = 0; j < 4; ++j) {
                uint32_t hi = f2tf32(f[j]);
                qhi[ks][j] = hi;
                qlo[ks][j] = f2tf32(f[j] - __uint_as_float(hi));
            }
        }
    }

    const int sqr0 = sid[q0 + wrow + g];
    const int sqr1 = sid[q0 + wrow + g + 8];
    const int sqmin = sid[q0], sqmax = sid[q0 + QT - 1];

    float o[8][4] = {};
    float m0 = -1e30f, m1 = -1e30f, l0 = 0.f, l1 = 0.f;

    for (int k0 = 0; k0 < LL; k0 += KT2) {
        int kmin = sid[k0], kmax = sid[k0 + KT2 - 1];
        if (kmax < sqmin || kmin > sqmax) continue;

        __syncthreads();

#pragma unroll
        for (int it = 0; it < 4; ++it) {
            int idx = tid + it * 128;
            int ki = idx >> 4;
            int dc = (idx & 15) << 2;
            float4 v = *reinterpret_cast<const float4*>(kbase + (size_t)(k0 + ki) * DHD + dc);
            float f[4] = {v.x, v.y, v.z, v.w};
#pragma unroll
            for (int j = 0; j < 4; ++j) {
                int p = perm_k(dc + j);
                uint32_t hi = f2tf32(f[j]);
                Khi[ki][p] = hi;
                Klo[ki][p] = f2tf32(f[j] - __uint_as_float(hi));
            }
        }
#pragma unroll
        for (int it = 0; it < 4; ++it) {
            int idx = tid + it * 128;
            int ki = idx & 31;
            int dc = ((idx >> 5) & 15) << 2;
            int pk = perm_k(ki);
            float4 v = *reinterpret_cast<const float4*>(vbase + (size_t)(k0 + ki) * DHD + dc);
            float f[4] = {v.x, v.y, v.z, v.w};
#pragma unroll
            for (int j = 0; j < 4; ++j) {
                uint32_t hi = f2tf32(f[j]);
                Vth[dc + j][pk] = hi;
                Vtl[dc + j][pk] = f2tf32(f[j] - __uint_as_float(hi));
            }
        }
        if (tid < KT2) sk_s[tid] = sid[k0 + tid];
        __syncthreads();

        float s[4][4] = {};
#pragma unroll
        for (int ks = 0; ks < 8; ++ks) {
#pragma unroll
            for (int nt = 0; nt < 4; ++nt) {
                uint2 bh2 = *reinterpret_cast<const uint2*>(&Khi[nt * 8 + g][8 * ks + 2 * tg]);
                uint2 bl2 = *reinterpret_cast<const uint2*>(&Klo[nt * 8 + g][8 * ks + 2 * tg]);
                uint32_t bh[2] = {bh2.x, bh2.y};
                uint32_t bl[2] = {bl2.x, bl2.y};
                mma_tf32(s[nt], qhi[ks], bh);
                mma_tf32(s[nt], qlo[ks], bh);
                mma_tf32(s[nt], qhi[ks], bl);
            }
        }

#pragma unroll
        for (int nt = 0; nt < 4; ++nt) {
            int c = nt * 8 + 2 * tg;
            int sk0 = sk_s[c], sk1 = sk_s[c + 1];
            if (sqr0 != sk0) s[nt][0] = -1e30f;
            if (sqr0 != sk1) s[nt][1] = -1e30f;
            if (sqr1 != sk0) s[nt][2] = -1e30f;
            if (sqr1 != sk1) s[nt][3] = -1e30f;
        }

        float mx0 = -1e30f, mx1 = -1e30f;
#pragma unroll
        for (int nt = 0; nt < 4; ++nt) {
            mx0 = fmaxf(mx0, fmaxf(s[nt][0], s[nt][1]));
            mx1 = fmaxf(mx1, fmaxf(s[nt][2], s[nt][3]));
        }
        mx0 = fmaxf(mx0, __shfl_xor_sync(0xffffffffu, mx0, 1));
        mx0 = fmaxf(mx0, __shfl_xor_sync(0xffffffffu, mx0, 2));
        mx1 = fmaxf(mx1, __shfl_xor_sync(0xffffffffu, mx1, 1));
        mx1 = fmaxf(mx1, __shfl_xor_sync(0xffffffffu, mx1, 2));
        float mn0 = fmaxf(m0, mx0), mn1 = fmaxf(m1, mx1);
        float al0 = __expf(m0 - mn0), al1 = __expf(m1 - mn1);
        float ps0 = 0.f, ps1 = 0.f;
#pragma unroll
        for (int nt = 0; nt < 4; ++nt) {
            float p00 = (s[nt][0] < -1e29f) ? 0.f : __expf(s[nt][0] - mn0);
            float p01 = (s[nt][1] < -1e29f) ? 0.f : __expf(s[nt][1] - mn0);
            float p10 = (s[nt][2] < -1e29f) ? 0.f : __expf(s[nt][2] - mn1);
            float p11 = (s[nt][3] < -1e29f) ? 0.f : __expf(s[nt][3] - mn1);
            s[nt][0] = p00; s[nt][1] = p01; s[nt][2] = p10; s[nt][3] = p11;
            ps0 += p00 + p01;
            ps1 += p10 + p11;
        }
        ps0 += __shfl_xor_sync(0xffffffffu, ps0, 1);
        ps0 += __shfl_xor_sync(0xffffffffu, ps0, 2);
        ps1 += __shfl_xor_sync(0xffffffffu, ps1, 1);
        ps1 += __shfl_xor_sync(0xffffffffu, ps1, 2);
        l0 = l0 * al0 + ps0;
        l1 = l1 * al1 + ps1;
        m0 = mn0; m1 = mn1;

#pragma unroll
        for (int dt = 0; dt < 8; ++dt) {
            o[dt][0] *= al0; o[dt][1] *= al0;
            o[dt][2] *= al1; o[dt][3] *= al1;
        }

#pragma unroll
        for (int nt = 0; nt < 4; ++nt) {
            int s0l = (lane & ~3) | (tg >> 1);
            int s1l = s0l + 2;
            float e0 = __shfl_sync(0xffffffffu, s[nt][0], s0l);
            float e1 = __shfl_sync(0xffffffffu, s[nt][1], s0l);
            float e2 = __shfl_sync(0xffffffffu, s[nt][2], s0l);
            float e3 = __shfl_sync(0xffffffffu, s[nt][3], s0l);
            float f0 = __shfl_sync(0xffffffffu, s[nt][0], s1l);
            float f1 = __shfl_sync(0xffffffffu, s[nt][1], s1l);
            float f2 = __shfl_sync(0xffffffffu, s[nt][2], s1l);
            float f3 = __shfl_sync(0xffffffffu, s[nt][3], s1l);
            bool odd = (tg & 1);
            float a0f = odd ? e1 : e0;
            float a1f = odd ? e3 : e2;
            float a2f = odd ? f1 : f0;
            float a3f = odd ? f3 : f2;
            uint32_t ah[4], alr[4];
            ah[0] = f2tf32(a0f); alr[0] = f2tf32(a0f - __uint_as_float(ah[0]));
            ah[1] = f2tf32(a1f); alr[1] = f2tf32(a1f - __uint_as_float(ah[1]));
            ah[2] = f2tf32(a2f); alr[2] = f2tf32(a2f - __uint_as_float(ah[2]));
            ah[3] = f2tf32(a3f); alr[3] = f2tf32(a3f - __uint_as_float(ah[3]));
#pragma unroll
            for (int dt = 0; dt < 8; ++dt) {
                uint2 vh2 = *reinterpret_cast<const uint2*>(&Vth[dt * 8 + g][8 * nt + 2 * tg]);
                uint2 vl2 = *reinterpret_cast<const uint2*>(&Vtl[dt * 8 + g][8 * nt + 2 * tg]);
                uint32_t bh[2] = {vh2.x, vh2.y};
                uint32_t bl[2] = {vl2.x, vl2.y};
                mma_tf32(o[dt], ah, bh);
                mma_tf32(o[dt], alr, bh);
                mma_tf32(o[dt], ah, bl);
            }
        }
    }

    // epilogue: pre-round ctx to tf32 grid (feeds the raw-bit out-proj GEMM)
    float invl0 = 1.f / l0, invl1 = 1.f / l1;
    size_t row0 = ((size_t)b * LL + q0 + wrow + g) * DD + h * DHD;
    size_t row1 = ((size_t)b * LL + q0 + wrow + g + 8) * DD + h * DHD;
#pragma unroll
    for (int dt = 0; dt < 8; ++dt) {
        int col = dt * 8 + 2 * tg;
        *reinterpret_cast<float2*>(ctx + row0 + col) =
            make_float2(rnd_tf32(o[dt][0] * invl0), rnd_tf32(o[dt][1] * invl0));
        *reinterpret_cast<float2*>(ctx + row1 + col) =
            make_float2(rnd_tf32(o[dt][2] * invl1), rnd_tf32(o[dt][3] * invl1));
    }
}

// -------------------- launch --------------------
extern "C" void kernel_launch(void* const* d_in, const int* in_sizes, int n_in,
                              void* d_out, int out_size) {
    const float* x      = (const float*)d_in[0];
    const int*   seq    = (const int*)  d_in[1];
    const float* ln_w   = (const float*)d_in[2];
    const float* ln_b   = (const float*)d_in[3];
    const float* w_qkv  = (const float*)d_in[4];
    const float* qa     = (const float*)d_in[5];
    const float* qb     = (const float*)d_in[6];
    const float* va     = (const float*)d_in[7];
    const float* vb     = (const float*)d_in[8];
    const float* q_ln_w = (const float*)d_in[9];
    const float* k_ln_w = (const float*)d_in[10];
    const float* w_out  = (const float*)d_in[11];
    float* out = (float*)d_out;

    float *ph, *pweff, *pqkv, *pq, *pk, *pv, *pctx, *prc, *prs, *pwo;
    cudaGetSymbolAddress((void**)&ph,    g_h);
    cudaGetSymbolAddress((void**)&pweff, g_weff);
    cudaGetSymbolAddress((void**)&pqkv,  g_qkv);
    cudaGetSymbolAddress((void**)&pq,    g_q);
    cudaGetSymbolAddress((void**)&pk,    g_k);
    cudaGetSymbolAddress((void**)&pv,    g_v);
    cudaGetSymbolAddress((void**)&pctx,  g_ctx);
    cudaGetSymbolAddress((void**)&prc,   g_rcos);
    cudaGetSymbolAddress((void**)&prs,   g_rsin);
    cudaGetSymbolAddress((void**)&pwo,   g_wout_r);

    cudaFuncSetAttribute(gemm_tf32, cudaFuncAttributeMaxDynamicSharedMemorySize, SMEM_GEMM);

    rope_table_kernel<<<(LL * 32 + 255) / 256, 256>>>(prc, prs);
    ln_kernel<<<NROWS, 256>>>(x, ln_w, ln_b, ph);
    weff_kernel<<<(4 * DD * DD + 255) / 256, 256>>>(w_qkv, qa, qb, va, vb, w_out, pwo, pweff);
    gemm_tf32<<<dim3(3 * DD / BN, NROWS / BM), 128, SMEM_GEMM>>>(ph, pweff, pqkv, NROWS, 3 * DD, DD);
    transform_kernel<<<NROWS, 256>>>(pqkv, q_ln_w, k_ln_w, prc, prs, pq, pk, pv);
    attn_tc_kernel<<<dim3(LL / QT, HH, BB), 128>>>(pq, pk, pv, seq, pctx);
    gemm_tf32<<<dim3(DD / BN, NROWS / BM), 128, SMEM_GEMM>>>(pctx, pwo, out, NROWS, DD, DD);
}

// round 13
// speedup vs baseline: 1.1072x; 1.1072x over previous
#include <cuda_runtime.h>
#include <math.h>
#include <stddef.h>
#include <stdint.h>

// Problem constants
#define BB 2
#define LL 2048
#define DD 1024
#define HH 16
#define DHD 64
#define RR 32
#define NROWS (BB*LL)          // 4096
#define LORA_SCALE 2.0f
#define ATTN_SCALE 0.125f      // 1/sqrt(64)

// -------------------- scratch (static device memory, allowed) --------------------
__device__ float g_h[NROWS * DD];          // tf32-rounded LN(x)
__device__ float g_weff[3 * DD * DD];      // tf32-rounded qkv weight + lora
__device__ float g_qkv[NROWS * 3 * DD];
__device__ float g_q[BB * HH * LL * DHD];  // [B,H,L,DH]
__device__ float g_k[BB * HH * LL * DHD];
__device__ float g_v[BB * HH * LL * DHD];
__device__ float g_ctx[NROWS * DD];        // tf32-rounded attention output
__device__ float g_rcos[LL * 32];
__device__ float g_rsin[LL * 32];
__device__ float g_wout_r[DD * DD];        // tf32-rounded w_out

// -------------------- helpers --------------------
__device__ __forceinline__ uint32_t f2tf32(float f) {
    uint32_t r;
    asm("cvt.rna.tf32.f32 %0, %1;" : "=r"(r) : "f"(f));
    return r;
}
__device__ __forceinline__ float rnd_tf32(float f) {
    return __uint_as_float(f2tf32(f));
}

__device__ __forceinline__ void mma_tf32(float* c, const uint32_t* a, const uint32_t* b) {
    asm volatile(
        "mma.sync.aligned.m16n8k8.row.col.f32.tf32.tf32.f32 "
        "{%0,%1,%2,%3}, {%4,%5,%6,%7}, {%8,%9}, {%0,%1,%2,%3};\n"
        : "+f"(c[0]), "+f"(c[1]), "+f"(c[2]), "+f"(c[3])
        : "r"(a[0]), "r"(a[1]), "r"(a[2]), "r"(a[3]), "r"(b[0]), "r"(b[1]));
}

__device__ __forceinline__ void cp_async16(uint32_t saddr, const void* gptr) {
    asm volatile("cp.async.ca.shared.global [%0], [%1], 16;\n" :: "r"(saddr), "l"(gptr));
}
__device__ __forceinline__ void cp_commit() {
    asm volatile("cp.async.commit_group;\n");
}
template<int N>
__device__ __forceinline__ void cp_wait() {
    asm volatile("cp.async.wait_group %0;\n" :: "n"(N));
}

__device__ __forceinline__ float4 block_reduce4(float4 v, float4* buf) {
#pragma unroll
    for (int o = 16; o; o >>= 1) {
        v.x += __shfl_xor_sync(0xffffffffu, v.x, o);
        v.y += __shfl_xor_sync(0xffffffffu, v.y, o);
        v.z += __shfl_xor_sync(0xffffffffu, v.z, o);
        v.w += __shfl_xor_sync(0xffffffffu, v.w, o);
    }
    int w = threadIdx.x >> 5, lane = threadIdx.x & 31;
    if (lane == 0) buf[w] = v;
    __syncthreads();
    if (w == 0) {
        v = (lane < 8) ? buf[lane] : make_float4(0.f, 0.f, 0.f, 0.f);
#pragma unroll
        for (int o = 4; o; o >>= 1) {
            v.x += __shfl_xor_sync(0xffffffffu, v.x, o);
            v.y += __shfl_xor_sync(0xffffffffu, v.y, o);
            v.z += __shfl_xor_sync(0xffffffffu, v.z, o);
            v.w += __shfl_xor_sync(0xffffffffu, v.w, o);
        }
        if (lane == 0) buf[0] = v;
    }
    __syncthreads();
    return buf[0];
}

// -------------------- 0) RoPE table --------------------
__global__ void rope_table_kernel(float* __restrict__ rc, float* __restrict__ rs) {
    int i = blockIdx.x * blockDim.x + threadIdx.x;
    if (i >= LL * 32) return;
    int l = i >> 5, jj = i & 31;
    double invf = exp(-0.28782313662425575 * (double)jj);
    double ang = (double)l * invf;
    double sd, cd;
    sincos(ang, &sd, &cd);
    rc[i] = (float)cd;
    rs[i] = (float)sd;
}

// -------------------- 1) input LayerNorm (pre-rounded output) --------------------
__global__ void ln_kernel(const float* __restrict__ x, const float* __restrict__ w,
                          const float* __restrict__ b, float* __restrict__ out) {
    __shared__ float4 buf[8];
    int n = blockIdx.x;
    int tid = threadIdx.x;
    const float4* xr = reinterpret_cast<const float4*>(x + (size_t)n * DD);
    float4 xv = xr[tid];
    float4 sums = make_float4(xv.x + xv.y + xv.z + xv.w,
                              xv.x * xv.x + xv.y * xv.y + xv.z * xv.z + xv.w * xv.w,
                              0.f, 0.f);
    float4 r = block_reduce4(sums, buf);
    float mu = r.x * (1.f / DD);
    float var = r.y * (1.f / DD) - mu * mu;
    float inv = rsqrtf(var + 1e-5f);
    float4 wv = reinterpret_cast<const float4*>(w)[tid];
    float4 bv = reinterpret_cast<const float4*>(b)[tid];
    float4 o;
    o.x = rnd_tf32((xv.x - mu) * inv * wv.x + bv.x);
    o.y = rnd_tf32((xv.y - mu) * inv * wv.y + bv.y);
    o.z = rnd_tf32((xv.z - mu) * inv * wv.z + bv.z);
    o.w = rnd_tf32((xv.w - mu) * inv * wv.w + bv.w);
    reinterpret_cast<float4*>(out + (size_t)n * DD)[tid] = o;
}

// -------------------- 2) fold LoRA into QKV weight + round w_out (fused) ----------
__global__ void weff_kernel(const float* __restrict__ wqkv,
                            const float* __restrict__ qa, const float* __restrict__ qb,
                            const float* __restrict__ va, const float* __restrict__ vb,
                            const float* __restrict__ wout, float* __restrict__ woutr,
                            float* __restrict__ weff) {
    int idx = blockIdx.x * blockDim.x + threadIdx.x;
    if (idx >= 4 * DD * DD) return;
    if (idx >= 3 * DD * DD) {                 // tail: round w_out
        int i = idx - 3 * DD * DD;
        woutr[i] = rnd_tf32(wout[i]);
        return;
    }
    int e = idx >> 10, d = idx & 1023;
    float w = wqkv[idx];
    if (e < DD) {
        float s = 0.f;
#pragma unroll
        for (int r = 0; r < RR; ++r) s += qb[e * RR + r] * qa[r * DD + d];
        w += LORA_SCALE * s;
    } else if (e >= 2 * DD) {
        int eb = e - 2 * DD;
        float s = 0.f;
#pragma unroll
        for (int r = 0; r < RR; ++r) s += vb[eb * RR + r] * va[r * DD + d];
        w += LORA_SCALE * s;
    }
    weff[idx] = rnd_tf32(w);
}

// -------------------- 3/6) TF32 GEMM: 4 warps, 64x64 warp tile (R11 exact) ------
#define BM 128
#define BN 128
#define BK 16
#define SKW (BK + 8)   // 24
#define GSTG 3
#define SMEM_GEMM (GSTG * 2 * BM * SKW * 4)   // 73728 bytes

#define AS(s, r, c) sm_a[((s) * BM + (r)) * SKW + (c)]
#define WS(s, r, c) sm_w[((s) * BN + (r)) * SKW + (c)]

__global__ void __launch_bounds__(128, 2) gemm_tf32(const float* __restrict__ A,
                                                    const float* __restrict__ W,
                                                    float* __restrict__ C,
                                                    int M, int N, int K) {
    extern __shared__ uint32_t sm[];
    uint32_t* sm_a = sm;
    uint32_t* sm_w = sm + GSTG * BM * SKW;

    const int tid = threadIdx.x;
    const int lane = tid & 31;
    const int wid = tid >> 5;               // 0..3
    const int g = lane >> 2, tg = lane & 3;
    const int wm = wid >> 1, wn = wid & 1;  // 2 x 2 warp grid, 64x64 warp tile
    const int bm = blockIdx.y * BM, bn = blockIdx.x * BN;

    int row_[4], kc_[4];
#pragma unroll
    for (int l = 0; l < 4; ++l) {
        int idx = tid + l * 128;
        row_[l] = idx >> 2;
        kc_[l] = (idx & 3) << 2;
    }

    const float* gA = A + (size_t)bm * K;
    const float* gW = W + (size_t)bn * K;

    auto issue = [&](int s, int t) {
#pragma unroll
        for (int l = 0; l < 4; ++l) {
            uint32_t sa = (uint32_t)__cvta_generic_to_shared(&AS(s, row_[l], kc_[l]));
            cp_async16(sa, gA + (size_t)row_[l] * K + t * BK + kc_[l]);
            uint32_t sw = (uint32_t)__cvta_generic_to_shared(&WS(s, row_[l], kc_[l]));
            cp_async16(sw, gW + (size_t)row_[l] * K + t * BK + kc_[l]);
        }
        cp_commit();
    };

    const int nk = K / BK;
    issue(0, 0);
    issue(1, 1);

    float c[4][8][4] = {};

    for (int t = 0; t < nk; ++t) {
        if (t + 2 < nk) cp_wait<1>(); else cp_wait<0>();
        __syncthreads();
        if (t + 2 < nk) issue((t + 2) % GSTG, t + 2);

        const int buf = t % GSTG;
#pragma unroll
        for (int ks = 0; ks < BK; ks += 8) {
            uint32_t af[4][4], bf[8][2];
#pragma unroll
            for (int mt = 0; mt < 4; ++mt) {
                int m = wm * 64 + mt * 16;
                uint2 a0 = *reinterpret_cast<const uint2*>(&AS(buf, m + g,     ks + 2 * tg));
                uint2 a1 = *reinterpret_cast<const uint2*>(&AS(buf, m + g + 8, ks + 2 * tg));
                af[mt][0] = a0.x; af[mt][2] = a0.y;
                af[mt][1] = a1.x; af[mt][3] = a1.y;
            }
#pragma unroll
            for (int nt = 0; nt < 8; ++nt) {
                int n = wn * 64 + nt * 8;
                uint2 b0 = *reinterpret_cast<const uint2*>(&WS(buf, n + g, ks + 2 * tg));
                bf[nt][0] = b0.x; bf[nt][1] = b0.y;
            }
#pragma unroll
            for (int mt = 0; mt < 4; ++mt)
#pragma unroll
                for (int nt = 0; nt < 8; ++nt)
                    mma_tf32(c[mt][nt], af[mt], bf[nt]);
        }
    }

#pragma unroll
    for (int mt = 0; mt < 4; ++mt) {
        int row0 = bm + wm * 64 + mt * 16 + g;
#pragma unroll
        for (int nt = 0; nt < 8; ++nt) {
            int col = bn + wn * 64 + nt * 8 + 2 * tg;
            *reinterpret_cast<float2*>(C + (size_t)row0 * N + col) =
                make_float2(c[mt][nt][0], c[mt][nt][1]);
            *reinterpret_cast<float2*>(C + (size_t)(row0 + 8) * N + col) =
                make_float2(c[mt][nt][2], c[mt][nt][3]);
        }
    }
}

// -------------------- 4) q/k LN + RoPE + head transpose --------------------
__global__ void transform_kernel(const float* __restrict__ qkv,
                                 const float* __restrict__ qw, const float* __restrict__ kw,
                                 const float* __restrict__ rcos, const float* __restrict__ rsin,
                                 float* __restrict__ gq, float* __restrict__ gk,
                                 float* __restrict__ gv) {
    __shared__ float sq[DD];
    __shared__ float sk[DD];
    __shared__ float4 buf[8];
    int n = blockIdx.x;
    int b = n >> 11, l = n & 2047;
    int tid = threadIdx.x;
    const float* row = qkv + (size_t)n * (3 * DD);
    float4 qv = reinterpret_cast<const float4*>(row)[tid];
    float4 kv = reinterpret_cast<const float4*>(row + DD)[tid];
    float4 vv = reinterpret_cast<const float4*>(row + 2 * DD)[tid];

    {
        int d = tid * 4;
        int h = d >> 6, j = d & 63;
        float* dst = gv + ((((size_t)b * HH + h) * LL + l) * DHD + j);
        *reinterpret_cast<float4*>(dst) = vv;
    }

    float4 sums = make_float4(qv.x + qv.y + qv.z + qv.w,
                              qv.x * qv.x + qv.y * qv.y + qv.z * qv.z + qv.w * qv.w,
                              kv.x + kv.y + kv.z + kv.w,
                              kv.x * kv.x + kv.y * kv.y + kv.z * kv.z + kv.w * kv.w);
    float4 r = block_reduce4(sums, buf);
    float muq = r.x * (1.f / DD), ivq = rsqrtf(r.y * (1.f / DD) - muq * muq + 1e-5f);
    float muk = r.z * (1.f / DD), ivk = rsqrtf(r.w * (1.f / DD) - muk * muk + 1e-5f);
    float4 qwv = reinterpret_cast<const float4*>(qw)[tid];
    float4 kwv = reinterpret_cast<const float4*>(kw)[tid];
    int d0 = tid * 4;
    sq[d0 + 0] = (qv.x - muq) * ivq * qwv.x;
    sq[d0 + 1] = (qv.y - muq) * ivq * qwv.y;
    sq[d0 + 2] = (qv.z - muq) * ivq * qwv.z;
    sq[d0 + 3] = (qv.w - muq) * ivq * qwv.w;
    sk[d0 + 0] = (kv.x - muk) * ivk * kwv.x;
    sk[d0 + 1] = (kv.y - muk) * ivk * kwv.y;
    sk[d0 + 2] = (kv.z - muk) * ivk * kwv.z;
    sk[d0 + 3] = (kv.w - muk) * ivk * kwv.w;
    __syncthreads();

    float oq[4], ok[4];
#pragma unroll
    for (int c = 0; c < 4; ++c) {
        int d = d0 + c;
        int j = d & 63;
        int jj = j & 31;
        float cs = rcos[l * 32 + jj];
        float sn = rsin[l * 32 + jj];
        if (j < 32) {
            oq[c] = sq[d] * cs - sq[d + 32] * sn;
            ok[c] = sk[d] * cs - sk[d + 32] * sn;
        } else {
            oq[c] = sq[d] * cs + sq[d - 32] * sn;
            ok[c] = sk[d] * cs + sk[d - 32] * sn;
        }
    }
    int h = d0 >> 6, j = d0 & 63;
    size_t base = (((size_t)b * HH + h) * LL + l) * DHD + j;
    *reinterpret_cast<float4*>(gq + base) = make_float4(oq[0], oq[1], oq[2], oq[3]);
    *reinterpret_cast<float4*>(gk + base) = make_float4(ok[0], ok[1], ok[2], ok[3]);
}

// -------------------- 5) tensor-core flash attention (3xTF32, R7/R11 exact) --------
#define QT 64
#define KT2 32
#define KPAD 72
#define VPAD 40

__device__ __forceinline__ int perm_k(int d) {
    return 8 * (d >> 3) + 2 * (d & 3) + ((d >> 2) & 1);
}

__global__ void __launch_bounds__(128) attn_tc_kernel(const float* __restrict__ gq,
                                                      const float* __restrict__ gk,
                                                      const float* __restrict__ gv,
                                                      const int* __restrict__ seq_id,
                                                      float* __restrict__ ctx) {
    __shared__ __align__(16) uint32_t Khi[KT2][KPAD];
    __shared__ __align__(16) uint32_t Klo[KT2][KPAD];
    __shared__ __align__(16) uint32_t Vth[DHD][VPAD];
    __shared__ __align__(16) uint32_t Vtl[DHD][VPAD];
    __shared__ int sk_s[KT2];

    const int q0 = blockIdx.x * QT;
    const int h = blockIdx.y;
    const int b = blockIdx.z;
    const float* qbase = gq + (((size_t)b * HH + h) * LL) * DHD;
    const float* kbase = gk + (((size_t)b * HH + h) * LL) * DHD;
    const float* vbase = gv + (((size_t)b * HH + h) * LL) * DHD;
    const int* sid = seq_id + (size_t)b * LL;

    const int tid = threadIdx.x;
    const int lane = tid & 31;
    const int wid = tid >> 5;
    const int g = lane >> 2, tg = lane & 3;
    const int wrow = wid * 16;

    uint32_t qhi[8][4], qlo[8][4];
    {
        const float* r0 = qbase + (size_t)(q0 + wrow + g) * DHD;
        const float* r1 = qbase + (size_t)(q0 + wrow + g + 8) * DHD;
#pragma unroll
        for (int ks = 0; ks < 8; ++ks) {
            float f[4];
            f[0] = r0[ks * 8 + tg]     * ATTN_SCALE;
            f[1] = r1[ks * 8 + tg]     * ATTN_SCALE;
            f[2] = r0[ks * 8 + tg + 4] * ATTN_SCALE;
            f[3] = r1[ks * 8 + tg + 4] * ATTN_SCALE;
#pragma unroll
            for (int j = 0; j < 4; ++j) {
                uint32_t hi = f2tf32(f[j]);
                qhi[ks][j] = hi;
                qlo[ks][j] = f2tf32(f[j] - __uint_as_float(hi));
            }
        }
    }

    const int sqr0 = sid[q0 + wrow + g];
    const int sqr1 = sid[q0 + wrow + g + 8];
    const int sqmin = sid[q0], sqmax = sid[q0 + QT - 1];

    float o[8][4] = {};
    float m0 = -1e30f, m1 = -1e30f, l0 = 0.f, l1 = 0.f;

    for (int k0 = 0; k0 < LL; k0 += KT2) {
        int kmin = sid[k0], kmax = sid[k0 + KT2 - 1];
        if (kmax < sqmin || kmin > sqmax) continue;

        __syncthreads();

#pragma unroll
        for (int it = 0; it < 4; ++it) {
            int idx = tid + it * 128;
            int ki = idx >> 4;
            int dc = (idx & 15) << 2;
            float4 v = *reinterpret_cast<const float4*>(kbase + (size_t)(k0 + ki) * DHD + dc);
            float f[4] = {v.x, v.y, v.z, v.w};
#pragma unroll
            for (int j = 0; j < 4; ++j) {
                int p = perm_k(dc + j);
                uint32_t hi = f2tf32(f[j]);
                Khi[ki][p] = hi;
                Klo[ki][p] = f2tf32(f[j] - __uint_as_float(hi));
            }
        }
#pragma unroll
        for (int it = 0; it < 4; ++it) {
            int idx = tid + it * 128;
            int ki = idx & 31;
            int dc = ((idx >> 5) & 15) << 2;
            int pk = perm_k(ki);
            float4 v = *reinterpret_cast<const float4*>(vbase + (size_t)(k0 + ki) * DHD + dc);
            float f[4] = {v.x, v.y, v.z, v.w};
#pragma unroll
            for (int j = 0; j < 4; ++j) {
                uint32_t hi = f2tf32(f[j]);
                Vth[dc + j][pk] = hi;
                Vtl[dc + j][pk] = f2tf32(f[j] - __uint_as_float(hi));
            }
        }
        if (tid < KT2) sk_s[tid] = sid[k0 + tid];
        __syncthreads();

        float s[4][4] = {};
#pragma unroll
        for (int ks = 0; ks < 8; ++ks) {
#pragma unroll
            for (int nt = 0; nt < 4; ++nt) {
                uint2 bh2 = *reinterpret_cast<const uint2*>(&Khi[nt * 8 + g][8 * ks + 2 * tg]);
                uint2 bl2 = *reinterpret_cast<const uint2*>(&Klo[nt * 8 + g][8 * ks + 2 * tg]);
                uint32_t bh[2] = {bh2.x, bh2.y};
                uint32_t bl[2] = {bl2.x, bl2.y};
                mma_tf32(s[nt], qhi[ks], bh);
                mma_tf32(s[nt], qlo[ks], bh);
                mma_tf32(s[nt], qhi[ks], bl);
            }
        }

#pragma unroll
        for (int nt = 0; nt < 4; ++nt) {
            int c = nt * 8 + 2 * tg;
            int sk0 = sk_s[c], sk1 = sk_s[c + 1];
            if (sqr0 != sk0) s[nt][0] = -1e30f;
            if (sqr0 != sk1) s[nt][1] = -1e30f;
            if (sqr1 != sk0) s[nt][2] = -1e30f;
            if (sqr1 != sk1) s[nt][3] = -1e30f;
        }

        float mx0 = -1e30f, mx1 = -1e30f;
#pragma unroll
        for (int nt = 0; nt < 4; ++nt) {
            mx0 = fmaxf(mx0, fmaxf(s[nt][0], s[nt][1]));
            mx1 = fmaxf(mx1, fmaxf(s[nt][2], s[nt][3]));
        }
        mx0 = fmaxf(mx0, __shfl_xor_sync(0xffffffffu, mx0, 1));
        mx0 = fmaxf(mx0, __shfl_xor_sync(0xffffffffu, mx0, 2));
        mx1 = fmaxf(mx1, __shfl_xor_sync(0xffffffffu, mx1, 1));
        mx1 = fmaxf(mx1, __shfl_xor_sync(0xffffffffu, mx1, 2));
        float mn0 = fmaxf(m0, mx0), mn1 = fmaxf(m1, mx1);
        float al0 = __expf(m0 - mn0), al1 = __expf(m1 - mn1);
        float ps0 = 0.f, ps1 = 0.f;
#pragma unroll
        for (int nt = 0; nt < 4; ++nt) {
            float p00 = (s[nt][0] < -1e29f) ? 0.f : __expf(s[nt][0] - mn0);
            float p01 = (s[nt][1] < -1e29f) ? 0.f : __expf(s[nt][1] - mn0);
            float p10 = (s[nt][2] < -1e29f) ? 0.f : __expf(s[nt][2] - mn1);
            float p11 = (s[nt][3] < -1e29f) ? 0.f : __expf(s[nt][3] - mn1);
            s[nt][0] = p00; s[nt][1] = p01; s[nt][2] = p10; s[nt][3] = p11;
            ps0 += p00 + p01;
            ps1 += p10 + p11;
        }
        ps0 += __shfl_xor_sync(0xffffffffu, ps0, 1);
        ps0 += __shfl_xor_sync(0xffffffffu, ps0, 2);
        ps1 += __shfl_xor_sync(0xffffffffu, ps1, 1);
        ps1 += __shfl_xor_sync(0xffffffffu, ps1, 2);
        l0 = l0 * al0 + ps0;
        l1 = l1 * al1 + ps1;
        m0 = mn0; m1 = mn1;

#pragma unroll
        for (int dt = 0; dt < 8; ++dt) {
            o[dt][0] *= al0; o[dt][1] *= al0;
            o[dt][2] *= al1; o[dt][3] *= al1;
        }

#pragma unroll
        for (int nt = 0; nt < 4; ++nt) {
            int s0l = (lane & ~3) | (tg >> 1);
            int s1l = s0l + 2;
            float e0 = __shfl_sync(0xffffffffu, s[nt][0], s0l);
            float e1 = __shfl_sync(0xffffffffu, s[nt][1], s0l);
            float e2 = __shfl_sync(0xffffffffu, s[nt][2], s0l);
            float e3 = __shfl_sync(0xffffffffu, s[nt][3], s0l);
            float f0 = __shfl_sync(0xffffffffu, s[nt][0], s1l);
            float f1 = __shfl_sync(0xffffffffu, s[nt][1], s1l);
            float f2 = __shfl_sync(0xffffffffu, s[nt][2], s1l);
            float f3 = __shfl_sync(0xffffffffu, s[nt][3], s1l);
            bool odd = (tg & 1);
            float a0f = odd ? e1 : e0;
            float a1f = odd ? e3 : e2;
            float a2f = odd ? f1 : f0;
            float a3f = odd ? f3 : f2;
            uint32_t ah[4], alr[4];
            ah[0] = f2tf32(a0f); alr[0] = f2tf32(a0f - __uint_as_float(ah[0]));
            ah[1] = f2tf32(a1f); alr[1] = f2tf32(a1f - __uint_as_float(ah[1]));
            ah[2] = f2tf32(a2f); alr[2] = f2tf32(a2f - __uint_as_float(ah[2]));
            ah[3] = f2tf32(a3f); alr[3] = f2tf32(a3f - __uint_as_float(ah[3]));
#pragma unroll
            for (int dt = 0; dt < 8; ++dt) {
                uint2 vh2 = *reinterpret_cast<const uint2*>(&Vth[dt * 8 + g][8 * nt + 2 * tg]);
                uint2 vl2 = *reinterpret_cast<const uint2*>(&Vtl[dt * 8 + g][8 * nt + 2 * tg]);
                uint32_t bh[2] = {vh2.x, vh2.y};
                uint32_t bl[2] = {vl2.x, vl2.y};
                mma_tf32(o[dt], ah, bh);
                mma_tf32(o[dt], alr, bh);
                mma_tf32(o[dt], ah, bl);
            }
        }
    }

    // epilogue: pre-round ctx to tf32 grid (feeds the raw-bit out-proj GEMM)
    float invl0 = 1.f / l0, invl1 = 1.f / l1;
    size_t row0 = ((size_t)b * LL + q0 + wrow + g) * DD + h * DHD;
    size_t row1 = ((size_t)b * LL + q0 + wrow + g + 8) * DD + h * DHD;
#pragma unroll
    for (int dt = 0; dt < 8; ++dt) {
        int col = dt * 8 + 2 * tg;
        *reinterpret_cast<float2*>(ctx + row0 + col) =
            make_float2(rnd_tf32(o[dt][0] * invl0), rnd_tf32(o[dt][1] * invl0));
        *reinterpret_cast<float2*>(ctx + row1 + col) =
            make_float2(rnd_tf32(o[dt][2] * invl1), rnd_tf32(o[dt][3] * invl1));
    }
}

// -------------------- launch --------------------
extern "C" void kernel_launch(void* const* d_in, const int* in_sizes, int n_in,
                              void* d_out, int out_size) {
    const float* x      = (const float*)d_in[0];
    const int*   seq    = (const int*)  d_in[1];
    const float* ln_w   = (const float*)d_in[2];
    const float* ln_b   = (const float*)d_in[3];
    const float* w_qkv  = (const float*)d_in[4];
    const float* qa     = (const float*)d_in[5];
    const float* qb     = (const float*)d_in[6];
    const float* va     = (const float*)d_in[7];
    const float* vb     = (const float*)d_in[8];
    const float* q_ln_w = (const float*)d_in[9];
    const float* k_ln_w = (const float*)d_in[10];
    const float* w_out  = (const float*)d_in[11];
    float* out = (float*)d_out;

    float *ph, *pweff, *pqkv, *pq, *pk, *pv, *pctx, *prc, *prs, *pwo;
    cudaGetSymbolAddress((void**)&ph,    g_h);
    cudaGetSymbolAddress((void**)&pweff, g_weff);
    cudaGetSymbolAddress((void**)&pqkv,  g_qkv);
    cudaGetSymbolAddress((void**)&pq,    g_q);
    cudaGetSymbolAddress((void**)&pk,    g_k);
    cudaGetSymbolAddress((void**)&pv,    g_v);
    cudaGetSymbolAddress((void**)&pctx,  g_ctx);
    cudaGetSymbolAddress((void**)&prc,   g_rcos);
    cudaGetSymbolAddress((void**)&prs,   g_rsin);
    cudaGetSymbolAddress((void**)&pwo,   g_wout_r);

    cudaFuncSetAttribute(gemm_tf32, cudaFuncAttributeMaxDynamicSharedMemorySize, SMEM_GEMM);

    rope_table_kernel<<<(LL * 32 + 255) / 256, 256>>>(prc, prs);
    ln_kernel<<<NROWS, 256>>>(x, ln_w, ln_b, ph);
    weff_kernel<<<(4 * DD * DD + 255) / 256, 256>>>(w_qkv, qa, qb, va, vb, w_out, pwo, pweff);
    gemm_tf32<<<dim3(3 * DD / BN, NROWS / BM), 128, SMEM_GEMM>>>(ph, pweff, pqkv, NROWS, 3 * DD, DD);
    transform_kernel<<<NROWS, 256>>>(pqkv, q_ln_w, k_ln_w, prc, prs, pq, pk, pv);
    attn_tc_kernel<<<dim3(LL / QT, HH, BB), 128>>>(pq, pk, pv, seq, pctx);
    gemm_tf32<<<dim3(DD / BN, NROWS / BM), 128, SMEM_GEMM>>>(pctx, pwo, out, NROWS, DD, DD);
}

// round 14
// speedup vs baseline: 1.2307x; 1.1116x over previous
#include <cuda_runtime.h>
#include <math.h>
#include <stddef.h>
#include <stdint.h>

// Problem constants
#define BB 2
#define LL 2048
#define DD 1024
#define HH 16
#define DHD 64
#define RR 32
#define NROWS (BB*LL)          // 4096
#define LORA_SCALE 2.0f
#define ATTN_SCALE 0.125f      // 1/sqrt(64)

// -------------------- scratch (static device memory, allowed) --------------------
__device__ float g_h[NROWS * DD];          // tf32-rounded LN(x)
__device__ float g_weff[3 * DD * DD];      // tf32-rounded qkv weight + lora
__device__ float g_qkv[NROWS * 3 * DD];
__device__ float g_q[BB * HH * LL * DHD];  // [B,H,L,DH]
__device__ float g_k[BB * HH * LL * DHD];
__device__ float g_v[BB * HH * LL * DHD];
__device__ float g_ctx[NROWS * DD];        // tf32-rounded attention output
__device__ float g_rcos[LL * 32];
__device__ float g_rsin[LL * 32];
__device__ float g_wout_r[DD * DD];        // tf32-rounded w_out

// -------------------- helpers --------------------
__device__ __forceinline__ uint32_t f2tf32(float f) {
    uint32_t r;
    asm("cvt.rna.tf32.f32 %0, %1;" : "=r"(r) : "f"(f));
    return r;
}
__device__ __forceinline__ float rnd_tf32(float f) {
    return __uint_as_float(f2tf32(f));
}

__device__ __forceinline__ void mma_tf32(float* c, const uint32_t* a, const uint32_t* b) {
    asm volatile(
        "mma.sync.aligned.m16n8k8.row.col.f32.tf32.tf32.f32 "
        "{%0,%1,%2,%3}, {%4,%5,%6,%7}, {%8,%9}, {%0,%1,%2,%3};\n"
        : "+f"(c[0]), "+f"(c[1]), "+f"(c[2]), "+f"(c[3])
        : "r"(a[0]), "r"(a[1]), "r"(a[2]), "r"(a[3]), "r"(b[0]), "r"(b[1]));
}

__device__ __forceinline__ void cp_async16(uint32_t saddr, const void* gptr) {
    asm volatile("cp.async.ca.shared.global [%0], [%1], 16;\n" :: "r"(saddr), "l"(gptr));
}
__device__ __forceinline__ void cp_commit() {
    asm volatile("cp.async.commit_group;\n");
}
template<int N>
__device__ __forceinline__ void cp_wait() {
    asm volatile("cp.async.wait_group %0;\n" :: "n"(N));
}

__device__ __forceinline__ float4 block_reduce4(float4 v, float4* buf) {
#pragma unroll
    for (int o = 16; o; o >>= 1) {
        v.x += __shfl_xor_sync(0xffffffffu, v.x, o);
        v.y += __shfl_xor_sync(0xffffffffu, v.y, o);
        v.z += __shfl_xor_sync(0xffffffffu, v.z, o);
        v.w += __shfl_xor_sync(0xffffffffu, v.w, o);
    }
    int w = threadIdx.x >> 5, lane = threadIdx.x & 31;
    if (lane == 0) buf[w] = v;
    __syncthreads();
    if (w == 0) {
        v = (lane < 8) ? buf[lane] : make_float4(0.f, 0.f, 0.f, 0.f);
#pragma unroll
        for (int o = 4; o; o >>= 1) {
            v.x += __shfl_xor_sync(0xffffffffu, v.x, o);
            v.y += __shfl_xor_sync(0xffffffffu, v.y, o);
            v.z += __shfl_xor_sync(0xffffffffu, v.z, o);
            v.w += __shfl_xor_sync(0xffffffffu, v.w, o);
        }
        if (lane == 0) buf[0] = v;
    }
    __syncthreads();
    return buf[0];
}

// -------------------- 0) RoPE table --------------------
__global__ void rope_table_kernel(float* __restrict__ rc, float* __restrict__ rs) {
    int i = blockIdx.x * blockDim.x + threadIdx.x;
    if (i >= LL * 32) return;
    int l = i >> 5, jj = i & 31;
    double invf = exp(-0.28782313662425575 * (double)jj);
    double ang = (double)l * invf;
    double sd, cd;
    sincos(ang, &sd, &cd);
    rc[i] = (float)cd;
    rs[i] = (float)sd;
}

// -------------------- 1) input LayerNorm (pre-rounded output) --------------------
__global__ void ln_kernel(const float* __restrict__ x, const float* __restrict__ w,
                          const float* __restrict__ b, float* __restrict__ out) {
    __shared__ float4 buf[8];
    int n = blockIdx.x;
    int tid = threadIdx.x;
    const float4* xr = reinterpret_cast<const float4*>(x + (size_t)n * DD);
    float4 xv = xr[tid];
    float4 sums = make_float4(xv.x + xv.y + xv.z + xv.w,
                              xv.x * xv.x + xv.y * xv.y + xv.z * xv.z + xv.w * xv.w,
                              0.f, 0.f);
    float4 r = block_reduce4(sums, buf);
    float mu = r.x * (1.f / DD);
    float var = r.y * (1.f / DD) - mu * mu;
    float inv = rsqrtf(var + 1e-5f);
    float4 wv = reinterpret_cast<const float4*>(w)[tid];
    float4 bv = reinterpret_cast<const float4*>(b)[tid];
    float4 o;
    o.x = rnd_tf32((xv.x - mu) * inv * wv.x + bv.x);
    o.y = rnd_tf32((xv.y - mu) * inv * wv.y + bv.y);
    o.z = rnd_tf32((xv.z - mu) * inv * wv.z + bv.z);
    o.w = rnd_tf32((xv.w - mu) * inv * wv.w + bv.w);
    reinterpret_cast<float4*>(out + (size_t)n * DD)[tid] = o;
}

// -------------------- 2) fold LoRA into QKV weight + round w_out (fused) ----------
__global__ void weff_kernel(const float* __restrict__ wqkv,
                            const float* __restrict__ qa, const float* __restrict__ qb,
                            const float* __restrict__ va, const float* __restrict__ vb,
                            const float* __restrict__ wout, float* __restrict__ woutr,
                            float* __restrict__ weff) {
    int idx = blockIdx.x * blockDim.x + threadIdx.x;
    if (idx >= 4 * DD * DD) return;
    if (idx >= 3 * DD * DD) {                 // tail: round w_out
        int i = idx - 3 * DD * DD;
        woutr[i] = rnd_tf32(wout[i]);
        return;
    }
    int e = idx >> 10, d = idx & 1023;
    float w = wqkv[idx];
    if (e < DD) {
        float s = 0.f;
#pragma unroll
        for (int r = 0; r < RR; ++r) s += qb[e * RR + r] * qa[r * DD + d];
        w += LORA_SCALE * s;
    } else if (e >= 2 * DD) {
        int eb = e - 2 * DD;
        float s = 0.f;
#pragma unroll
        for (int r = 0; r < RR; ++r) s += vb[eb * RR + r] * va[r * DD + d];
        w += LORA_SCALE * s;
    }
    weff[idx] = rnd_tf32(w);
}

// -------------------- 3/6) TF32 GEMM: 4 warps, 64x64 warp tile (R13 exact) ------
#define BM 128
#define BN 128
#define BK 16
#define SKW (BK + 8)   // 24
#define GSTG 3
#define SMEM_GEMM (GSTG * 2 * BM * SKW * 4)   // 73728 bytes

#define AS(s, r, c) sm_a[((s) * BM + (r)) * SKW + (c)]
#define WS(s, r, c) sm_w[((s) * BN + (r)) * SKW + (c)]

__global__ void __launch_bounds__(128, 2) gemm_tf32(const float* __restrict__ A,
                                                    const float* __restrict__ W,
                                                    float* __restrict__ C,
                                                    int M, int N, int K) {
    extern __shared__ uint32_t sm[];
    uint32_t* sm_a = sm;
    uint32_t* sm_w = sm + GSTG * BM * SKW;

    const int tid = threadIdx.x;
    const int lane = tid & 31;
    const int wid = tid >> 5;               // 0..3
    const int g = lane >> 2, tg = lane & 3;
    const int wm = wid >> 1, wn = wid & 1;  // 2 x 2 warp grid, 64x64 warp tile
    const int bm = blockIdx.y * BM, bn = blockIdx.x * BN;

    int row_[4], kc_[4];
#pragma unroll
    for (int l = 0; l < 4; ++l) {
        int idx = tid + l * 128;
        row_[l] = idx >> 2;
        kc_[l] = (idx & 3) << 2;
    }

    const float* gA = A + (size_t)bm * K;
    const float* gW = W + (size_t)bn * K;

    auto issue = [&](int s, int t) {
#pragma unroll
        for (int l = 0; l < 4; ++l) {
            uint32_t sa = (uint32_t)__cvta_generic_to_shared(&AS(s, row_[l], kc_[l]));
            cp_async16(sa, gA + (size_t)row_[l] * K + t * BK + kc_[l]);
            uint32_t sw = (uint32_t)__cvta_generic_to_shared(&WS(s, row_[l], kc_[l]));
            cp_async16(sw, gW + (size_t)row_[l] * K + t * BK + kc_[l]);
        }
        cp_commit();
    };

    const int nk = K / BK;
    issue(0, 0);
    issue(1, 1);

    float c[4][8][4] = {};

    for (int t = 0; t < nk; ++t) {
        if (t + 2 < nk) cp_wait<1>(); else cp_wait<0>();
        __syncthreads();
        if (t + 2 < nk) issue((t + 2) % GSTG, t + 2);

        const int buf = t % GSTG;
#pragma unroll
        for (int ks = 0; ks < BK; ks += 8) {
            uint32_t af[4][4], bf[8][2];
#pragma unroll
            for (int mt = 0; mt < 4; ++mt) {
                int m = wm * 64 + mt * 16;
                uint2 a0 = *reinterpret_cast<const uint2*>(&AS(buf, m + g,     ks + 2 * tg));
                uint2 a1 = *reinterpret_cast<const uint2*>(&AS(buf, m + g + 8, ks + 2 * tg));
                af[mt][0] = a0.x; af[mt][2] = a0.y;
                af[mt][1] = a1.x; af[mt][3] = a1.y;
            }
#pragma unroll
            for (int nt = 0; nt < 8; ++nt) {
                int n = wn * 64 + nt * 8;
                uint2 b0 = *reinterpret_cast<const uint2*>(&WS(buf, n + g, ks + 2 * tg));
                bf[nt][0] = b0.x; bf[nt][1] = b0.y;
            }
#pragma unroll
            for (int mt = 0; mt < 4; ++mt)
#pragma unroll
                for (int nt = 0; nt < 8; ++nt)
                    mma_tf32(c[mt][nt], af[mt], bf[nt]);
        }
    }

#pragma unroll
    for (int mt = 0; mt < 4; ++mt) {
        int row0 = bm + wm * 64 + mt * 16 + g;
#pragma unroll
        for (int nt = 0; nt < 8; ++nt) {
            int col = bn + wn * 64 + nt * 8 + 2 * tg;
            *reinterpret_cast<float2*>(C + (size_t)row0 * N + col) =
                make_float2(c[mt][nt][0], c[mt][nt][1]);
            *reinterpret_cast<float2*>(C + (size_t)(row0 + 8) * N + col) =
                make_float2(c[mt][nt][2], c[mt][nt][3]);
        }
    }
}

// -------------------- 4) q/k LN + RoPE + head transpose --------------------
__global__ void transform_kernel(const float* __restrict__ qkv,
                                 const float* __restrict__ qw, const float* __restrict__ kw,
                                 const float* __restrict__ rcos, const float* __restrict__ rsin,
                                 float* __restrict__ gq, float* __restrict__ gk,
                                 float* __restrict__ gv) {
    __shared__ float sq[DD];
    __shared__ float sk[DD];
    __shared__ float4 buf[8];
    int n = blockIdx.x;
    int b = n >> 11, l = n & 2047;
    int tid = threadIdx.x;
    const float* row = qkv + (size_t)n * (3 * DD);
    float4 qv = reinterpret_cast<const float4*>(row)[tid];
    float4 kv = reinterpret_cast<const float4*>(row + DD)[tid];
    float4 vv = reinterpret_cast<const float4*>(row + 2 * DD)[tid];

    {
        int d = tid * 4;
        int h = d >> 6, j = d & 63;
        float* dst = gv + ((((size_t)b * HH + h) * LL + l) * DHD + j);
        *reinterpret_cast<float4*>(dst) = vv;
    }

    float4 sums = make_float4(qv.x + qv.y + qv.z + qv.w,
                              qv.x * qv.x + qv.y * qv.y + qv.z * qv.z + qv.w * qv.w,
                              kv.x + kv.y + kv.z + kv.w,
                              kv.x * kv.x + kv.y * kv.y + kv.z * kv.z + kv.w * kv.w);
    float4 r = block_reduce4(sums, buf);
    float muq = r.x * (1.f / DD), ivq = rsqrtf(r.y * (1.f / DD) - muq * muq + 1e-5f);
    float muk = r.z * (1.f / DD), ivk = rsqrtf(r.w * (1.f / DD) - muk * muk + 1e-5f);
    float4 qwv = reinterpret_cast<const float4*>(qw)[tid];
    float4 kwv = reinterpret_cast<const float4*>(kw)[tid];
    int d0 = tid * 4;
    sq[d0 + 0] = (qv.x - muq) * ivq * qwv.x;
    sq[d0 + 1] = (qv.y - muq) * ivq * qwv.y;
    sq[d0 + 2] = (qv.z - muq) * ivq * qwv.z;
    sq[d0 + 3] = (qv.w - muq) * ivq * qwv.w;
    sk[d0 + 0] = (kv.x - muk) * ivk * kwv.x;
    sk[d0 + 1] = (kv.y - muk) * ivk * kwv.y;
    sk[d0 + 2] = (kv.z - muk) * ivk * kwv.z;
    sk[d0 + 3] = (kv.w - muk) * ivk * kwv.w;
    __syncthreads();

    float oq[4], ok[4];
#pragma unroll
    for (int c = 0; c < 4; ++c) {
        int d = d0 + c;
        int j = d & 63;
        int jj = j & 31;
        float cs = rcos[l * 32 + jj];
        float sn = rsin[l * 32 + jj];
        if (j < 32) {
            oq[c] = sq[d] * cs - sq[d + 32] * sn;
            ok[c] = sk[d] * cs - sk[d + 32] * sn;
        } else {
            oq[c] = sq[d] * cs + sq[d - 32] * sn;
            ok[c] = sk[d] * cs + sk[d - 32] * sn;
        }
    }
    int h = d0 >> 6, j = d0 & 63;
    size_t base = (((size_t)b * HH + h) * LL + l) * DHD + j;
    *reinterpret_cast<float4*>(gq + base) = make_float4(oq[0], oq[1], oq[2], oq[3]);
    *reinterpret_cast<float4*>(gk + base) = make_float4(ok[0], ok[1], ok[2], ok[3]);
}

// -------------------- 5) flash attention: S = 3xTF32, PV = plain TF32 --------------
#define QT 64
#define KT2 32
#define KPAD 72
#define VPAD 40

__device__ __forceinline__ int perm_k(int d) {
    return 8 * (d >> 3) + 2 * (d & 3) + ((d >> 2) & 1);
}

__global__ void __launch_bounds__(128) attn_tc_kernel(const float* __restrict__ gq,
                                                      const float* __restrict__ gk,
                                                      const float* __restrict__ gv,
                                                      const int* __restrict__ seq_id,
                                                      float* __restrict__ ctx) {
    __shared__ __align__(16) uint32_t Khi[KT2][KPAD];
    __shared__ __align__(16) uint32_t Klo[KT2][KPAD];
    __shared__ __align__(16) uint32_t Vth[DHD][VPAD];
    __shared__ int sk_s[KT2];

    const int q0 = blockIdx.x * QT;
    const int h = blockIdx.y;
    const int b = blockIdx.z;
    const float* qbase = gq + (((size_t)b * HH + h) * LL) * DHD;
    const float* kbase = gk + (((size_t)b * HH + h) * LL) * DHD;
    const float* vbase = gv + (((size_t)b * HH + h) * LL) * DHD;
    const int* sid = seq_id + (size_t)b * LL;

    const int tid = threadIdx.x;
    const int lane = tid & 31;
    const int wid = tid >> 5;
    const int g = lane >> 2, tg = lane & 3;
    const int wrow = wid * 16;

    uint32_t qhi[8][4], qlo[8][4];
    {
        const float* r0 = qbase + (size_t)(q0 + wrow + g) * DHD;
        const float* r1 = qbase + (size_t)(q0 + wrow + g + 8) * DHD;
#pragma unroll
        for (int ks = 0; ks < 8; ++ks) {
            float f[4];
            f[0] = r0[ks * 8 + tg]     * ATTN_SCALE;
            f[1] = r1[ks * 8 + tg]     * ATTN_SCALE;
            f[2] = r0[ks * 8 + tg + 4] * ATTN_SCALE;
            f[3] = r1[ks * 8 + tg + 4] * ATTN_SCALE;
#pragma unroll
            for (int j = 0; j < 4; ++j) {
                uint32_t hi = f2tf32(f[j]);
                qhi[ks][j] = hi;
                qlo[ks][j] = f2tf32(f[j] - __uint_as_float(hi));
            }
        }
    }

    const int sqr0 = sid[q0 + wrow + g];
    const int sqr1 = sid[q0 + wrow + g + 8];
    const int sqmin = sid[q0], sqmax = sid[q0 + QT - 1];

    float o[8][4] = {};
    float m0 = -1e30f, m1 = -1e30f, l0 = 0.f, l1 = 0.f;

    for (int k0 = 0; k0 < LL; k0 += KT2) {
        int kmin = sid[k0], kmax = sid[k0 + KT2 - 1];
        if (kmax < sqmin || kmin > sqmax) continue;

        __syncthreads();

        // K tile: 3x split (hi/lo), d-permuted
#pragma unroll
        for (int it = 0; it < 4; ++it) {
            int idx = tid + it * 128;
            int ki = idx >> 4;
            int dc = (idx & 15) << 2;
            float4 v = *reinterpret_cast<const float4*>(kbase + (size_t)(k0 + ki) * DHD + dc);
            float f[4] = {v.x, v.y, v.z, v.w};
#pragma unroll
            for (int j = 0; j < 4; ++j) {
                int p = perm_k(dc + j);
                uint32_t hi = f2tf32(f[j]);
                Khi[ki][p] = hi;
                Klo[ki][p] = f2tf32(f[j] - __uint_as_float(hi));
            }
        }
        // V tile: plain tf32 (hi only), transposed, k-permuted
#pragma unroll
        for (int it = 0; it < 4; ++it) {
            int idx = tid + it * 128;
            int ki = idx & 31;
            int dc = ((idx >> 5) & 15) << 2;
            int pk = perm_k(ki);
            float4 v = *reinterpret_cast<const float4*>(vbase + (size_t)(k0 + ki) * DHD + dc);
            Vth[dc + 0][pk] = f2tf32(v.x);
            Vth[dc + 1][pk] = f2tf32(v.y);
            Vth[dc + 2][pk] = f2tf32(v.z);
            Vth[dc + 3][pk] = f2tf32(v.w);
        }
        if (tid < KT2) sk_s[tid] = sid[k0 + tid];
        __syncthreads();

        // ---- S = Q K^T (3xTF32 — softmax needs accurate scores) ----
        float s[4][4] = {};
#pragma unroll
        for (int ks = 0; ks < 8; ++ks) {
#pragma unroll
            for (int nt = 0; nt < 4; ++nt) {
                uint2 bh2 = *reinterpret_cast<const uint2*>(&Khi[nt * 8 + g][8 * ks + 2 * tg]);
                uint2 bl2 = *reinterpret_cast<const uint2*>(&Klo[nt * 8 + g][8 * ks + 2 * tg]);
                uint32_t bh[2] = {bh2.x, bh2.y};
                uint32_t bl[2] = {bl2.x, bl2.y};
                mma_tf32(s[nt], qhi[ks], bh);
                mma_tf32(s[nt], qlo[ks], bh);
                mma_tf32(s[nt], qhi[ks], bl);
            }
        }

#pragma unroll
        for (int nt = 0; nt < 4; ++nt) {
            int c = nt * 8 + 2 * tg;
            int sk0 = sk_s[c], sk1 = sk_s[c + 1];
            if (sqr0 != sk0) s[nt][0] = -1e30f;
            if (sqr0 != sk1) s[nt][1] = -1e30f;
            if (sqr1 != sk0) s[nt][2] = -1e30f;
            if (sqr1 != sk1) s[nt][3] = -1e30f;
        }

        float mx0 = -1e30f, mx1 = -1e30f;
#pragma unroll
        for (int nt = 0; nt < 4; ++nt) {
            mx0 = fmaxf(mx0, fmaxf(s[nt][0], s[nt][1]));
            mx1 = fmaxf(mx1, fmaxf(s[nt][2], s[nt][3]));
        }
        mx0 = fmaxf(mx0, __shfl_xor_sync(0xffffffffu, mx0, 1));
        mx0 = fmaxf(mx0, __shfl_xor_sync(0xffffffffu, mx0, 2));
        mx1 = fmaxf(mx1, __shfl_xor_sync(0xffffffffu, mx1, 1));
        mx1 = fmaxf(mx1, __shfl_xor_sync(0xffffffffu, mx1, 2));
        float mn0 = fmaxf(m0, mx0), mn1 = fmaxf(m1, mx1);
        float al0 = __expf(m0 - mn0), al1 = __expf(m1 - mn1);
        float ps0 = 0.f, ps1 = 0.f;
#pragma unroll
        for (int nt = 0; nt < 4; ++nt) {
            float p00 = (s[nt][0] < -1e29f) ? 0.f : __expf(s[nt][0] - mn0);
            float p01 = (s[nt][1] < -1e29f) ? 0.f : __expf(s[nt][1] - mn0);
            float p10 = (s[nt][2] < -1e29f) ? 0.f : __expf(s[nt][2] - mn1);
            float p11 = (s[nt][3] < -1e29f) ? 0.f : __expf(s[nt][3] - mn1);
            s[nt][0] = p00; s[nt][1] = p01; s[nt][2] = p10; s[nt][3] = p11;
            ps0 += p00 + p01;
            ps1 += p10 + p11;
        }
        ps0 += __shfl_xor_sync(0xffffffffu, ps0, 1);
        ps0 += __shfl_xor_sync(0xffffffffu, ps0, 2);
        ps1 += __shfl_xor_sync(0xffffffffu, ps1, 1);
        ps1 += __shfl_xor_sync(0xffffffffu, ps1, 2);
        l0 = l0 * al0 + ps0;
        l1 = l1 * al1 + ps1;
        m0 = mn0; m1 = mn1;

#pragma unroll
        for (int dt = 0; dt < 8; ++dt) {
            o[dt][0] *= al0; o[dt][1] *= al0;
            o[dt][2] *= al1; o[dt][3] *= al1;
        }

        // ---- O += P V (plain TF32: P's and V's rounding residuals cancel in the sum)
#pragma unroll
        for (int nt = 0; nt < 4; ++nt) {
            int s0l = (lane & ~3) | (tg >> 1);
            int s1l = s0l + 2;
            float e0 = __shfl_sync(0xffffffffu, s[nt][0], s0l);
            float e1 = __shfl_sync(0xffffffffu, s[nt][1], s0l);
            float e2 = __shfl_sync(0xffffffffu, s[nt][2], s0l);
            float e3 = __shfl_sync(0xffffffffu, s[nt][3], s0l);
            float f0 = __shfl_sync(0xffffffffu, s[nt][0], s1l);
            float f1 = __shfl_sync(0xffffffffu, s[nt][1], s1l);
            float f2 = __shfl_sync(0xffffffffu, s[nt][2], s1l);
            float f3 = __shfl_sync(0xffffffffu, s[nt][3], s1l);
            bool odd = (tg & 1);
            float a0f = odd ? e1 : e0;
            float a1f = odd ? e3 : e2;
            float a2f = odd ? f1 : f0;
            float a3f = odd ? f3 : f2;
            uint32_t ah[4];
            ah[0] = f2tf32(a0f);
            ah[1] = f2tf32(a1f);
            ah[2] = f2tf32(a2f);
            ah[3] = f2tf32(a3f);
#pragma unroll
            for (int dt = 0; dt < 8; ++dt) {
                uint2 vh2 = *reinterpret_cast<const uint2*>(&Vth[dt * 8 + g][8 * nt + 2 * tg]);
                uint32_t bh[2] = {vh2.x, vh2.y};
                mma_tf32(o[dt], ah, bh);
            }
        }
    }

    // epilogue: pre-round ctx to tf32 grid (feeds the raw-bit out-proj GEMM)
    float invl0 = 1.f / l0, invl1 = 1.f / l1;
    size_t row0 = ((size_t)b * LL + q0 + wrow + g) * DD + h * DHD;
    size_t row1 = ((size_t)b * LL + q0 + wrow + g + 8) * DD + h * DHD;
#pragma unroll
    for (int dt = 0; dt < 8; ++dt) {
        int col = dt * 8 + 2 * tg;
        *reinterpret_cast<float2*>(ctx + row0 + col) =
            make_float2(rnd_tf32(o[dt][0] * invl0), rnd_tf32(o[dt][1] * invl0));
        *reinterpret_cast<float2*>(ctx + row1 + col) =
            make_float2(rnd_tf32(o[dt][2] * invl1), rnd_tf32(o[dt][3] * invl1));
    }
}

// -------------------- launch --------------------
extern "C" void kernel_launch(void* const* d_in, const int* in_sizes, int n_in,
                              void* d_out, int out_size) {
    const float* x      = (const float*)d_in[0];
    const int*   seq    = (const int*)  d_in[1];
    const float* ln_w   = (const float*)d_in[2];
    const float* ln_b   = (const float*)d_in[3];
    const float* w_qkv  = (const float*)d_in[4];
    const float* qa     = (const float*)d_in[5];
    const float* qb     = (const float*)d_in[6];
    const float* va     = (const float*)d_in[7];
    const float* vb     = (const float*)d_in[8];
    const float* q_ln_w = (const float*)d_in[9];
    const float* k_ln_w = (const float*)d_in[10];
    const float* w_out  = (const float*)d_in[11];
    float* out = (float*)d_out;

    float *ph, *pweff, *pqkv, *pq, *pk, *pv, *pctx, *prc, *prs, *pwo;
    cudaGetSymbolAddress((void**)&ph,    g_h);
    cudaGetSymbolAddress((void**)&pweff, g_weff);
    cudaGetSymbolAddress((void**)&pqkv,  g_qkv);
    cudaGetSymbolAddress((void**)&pq,    g_q);
    cudaGetSymbolAddress((void**)&pk,    g_k);
    cudaGetSymbolAddress((void**)&pv,    g_v);
    cudaGetSymbolAddress((void**)&pctx,  g_ctx);
    cudaGetSymbolAddress((void**)&prc,   g_rcos);
    cudaGetSymbolAddress((void**)&prs,   g_rsin);
    cudaGetSymbolAddress((void**)&pwo,   g_wout_r);

    cudaFuncSetAttribute(gemm_tf32, cudaFuncAttributeMaxDynamicSharedMemorySize, SMEM_GEMM);

    rope_table_kernel<<<(LL * 32 + 255) / 256, 256>>>(prc, prs);
    ln_kernel<<<NROWS, 256>>>(x, ln_w, ln_b, ph);
    weff_kernel<<<(4 * DD * DD + 255) / 256, 256>>>(w_qkv, qa, qb, va, vb, w_out, pwo, pweff);
    gemm_tf32<<<dim3(3 * DD / BN, NROWS / BM), 128, SMEM_GEMM>>>(ph, pweff, pqkv, NROWS, 3 * DD, DD);
    transform_kernel<<<NROWS, 256>>>(pqkv, q_ln_w, k_ln_w, prc, prs, pq, pk, pv);
    attn_tc_kernel<<<dim3(LL / QT, HH, BB), 128>>>(pq, pk, pv, seq, pctx);
    gemm_tf32<<<dim3(DD / BN, NROWS / BM), 128, SMEM_GEMM>>>(pctx, pwo, out, NROWS, DD, DD);
}

// round 15
// speedup vs baseline: 1.2368x; 1.0049x over previous
#include <cuda_runtime.h>
#include <math.h>
#include <stddef.h>
#include <stdint.h>

// Problem constants
#define BB 2
#define LL 2048
#define DD 1024
#define HH 16
#define DHD 64
#define RR 32
#define NROWS (BB*LL)          // 4096
#define LORA_SCALE 2.0f
#define ATTN_SCALE 0.125f      // 1/sqrt(64)

// -------------------- scratch (static device memory, allowed) --------------------
__device__ float g_h[NROWS * DD];          // tf32-rounded LN(x)
__device__ float g_weff[3 * DD * DD];      // tf32-rounded qkv weight + lora
__device__ float g_qkv[NROWS * 3 * DD];
__device__ float g_q[BB * HH * LL * DHD];  // [B,H,L,DH]
__device__ float g_k[BB * HH * LL * DHD];
__device__ float g_v[BB * HH * LL * DHD];
__device__ float g_ctx[NROWS * DD];        // tf32-rounded attention output
__device__ float g_rcos[LL * 32];
__device__ float g_rsin[LL * 32];
__device__ float g_wout_r[DD * DD];        // tf32-rounded w_out

// -------------------- helpers --------------------
__device__ __forceinline__ uint32_t f2tf32(float f) {
    uint32_t r;
    asm("cvt.rna.tf32.f32 %0, %1;" : "=r"(r) : "f"(f));
    return r;
}
__device__ __forceinline__ float rnd_tf32(float f) {
    return __uint_as_float(f2tf32(f));
}

__device__ __forceinline__ void mma_tf32(float* c, const uint32_t* a, const uint32_t* b) {
    asm volatile(
        "mma.sync.aligned.m16n8k8.row.col.f32.tf32.tf32.f32 "
        "{%0,%1,%2,%3}, {%4,%5,%6,%7}, {%8,%9}, {%0,%1,%2,%3};\n"
        : "+f"(c[0]), "+f"(c[1]), "+f"(c[2]), "+f"(c[3])
        : "r"(a[0]), "r"(a[1]), "r"(a[2]), "r"(a[3]), "r"(b[0]), "r"(b[1]));
}

__device__ __forceinline__ void cp_async16(uint32_t saddr, const void* gptr) {
    asm volatile("cp.async.ca.shared.global [%0], [%1], 16;\n" :: "r"(saddr), "l"(gptr));
}
__device__ __forceinline__ void cp_commit() {
    asm volatile("cp.async.commit_group;\n");
}
template<int N>
__device__ __forceinline__ void cp_wait() {
    asm volatile("cp.async.wait_group %0;\n" :: "n"(N));
}

__device__ __forceinline__ float4 block_reduce4(float4 v, float4* buf) {
#pragma unroll
    for (int o = 16; o; o >>= 1) {
        v.x += __shfl_xor_sync(0xffffffffu, v.x, o);
        v.y += __shfl_xor_sync(0xffffffffu, v.y, o);
        v.z += __shfl_xor_sync(0xffffffffu, v.z, o);
        v.w += __shfl_xor_sync(0xffffffffu, v.w, o);
    }
    int w = threadIdx.x >> 5, lane = threadIdx.x & 31;
    if (lane == 0) buf[w] = v;
    __syncthreads();
    if (w == 0) {
        v = (lane < 8) ? buf[lane] : make_float4(0.f, 0.f, 0.f, 0.f);
#pragma unroll
        for (int o = 4; o; o >>= 1) {
            v.x += __shfl_xor_sync(0xffffffffu, v.x, o);
            v.y += __shfl_xor_sync(0xffffffffu, v.y, o);
            v.z += __shfl_xor_sync(0xffffffffu, v.z, o);
            v.w += __shfl_xor_sync(0xffffffffu, v.w, o);
        }
        if (lane == 0) buf[0] = v;
    }
    __syncthreads();
    return buf[0];
}

// -------------------- 0) RoPE table --------------------
__global__ void rope_table_kernel(float* __restrict__ rc, float* __restrict__ rs) {
    int i = blockIdx.x * blockDim.x + threadIdx.x;
    if (i >= LL * 32) return;
    int l = i >> 5, jj = i & 31;
    double invf = exp(-0.28782313662425575 * (double)jj);
    double ang = (double)l * invf;
    double sd, cd;
    sincos(ang, &sd, &cd);
    rc[i] = (float)cd;
    rs[i] = (float)sd;
}

// -------------------- 1) input LayerNorm (pre-rounded output) --------------------
__global__ void ln_kernel(const float* __restrict__ x, const float* __restrict__ w,
                          const float* __restrict__ b, float* __restrict__ out) {
    __shared__ float4 buf[8];
    int n = blockIdx.x;
    int tid = threadIdx.x;
    const float4* xr = reinterpret_cast<const float4*>(x + (size_t)n * DD);
    float4 xv = xr[tid];
    float4 sums = make_float4(xv.x + xv.y + xv.z + xv.w,
                              xv.x * xv.x + xv.y * xv.y + xv.z * xv.z + xv.w * xv.w,
                              0.f, 0.f);
    float4 r = block_reduce4(sums, buf);
    float mu = r.x * (1.f / DD);
    float var = r.y * (1.f / DD) - mu * mu;
    float inv = rsqrtf(var + 1e-5f);
    float4 wv = reinterpret_cast<const float4*>(w)[tid];
    float4 bv = reinterpret_cast<const float4*>(b)[tid];
    float4 o;
    o.x = rnd_tf32((xv.x - mu) * inv * wv.x + bv.x);
    o.y = rnd_tf32((xv.y - mu) * inv * wv.y + bv.y);
    o.z = rnd_tf32((xv.z - mu) * inv * wv.z + bv.z);
    o.w = rnd_tf32((xv.w - mu) * inv * wv.w + bv.w);
    reinterpret_cast<float4*>(out + (size_t)n * DD)[tid] = o;
}

// -------------------- 2) fold LoRA into QKV weight + round w_out (fused) ----------
__global__ void weff_kernel(const float* __restrict__ wqkv,
                            const float* __restrict__ qa, const float* __restrict__ qb,
                            const float* __restrict__ va, const float* __restrict__ vb,
                            const float* __restrict__ wout, float* __restrict__ woutr,
                            float* __restrict__ weff) {
    int idx = blockIdx.x * blockDim.x + threadIdx.x;
    if (idx >= 4 * DD * DD) return;
    if (idx >= 3 * DD * DD) {                 // tail: round w_out
        int i = idx - 3 * DD * DD;
        woutr[i] = rnd_tf32(wout[i]);
        return;
    }
    int e = idx >> 10, d = idx & 1023;
    float w = wqkv[idx];
    if (e < DD) {
        float s = 0.f;
#pragma unroll
        for (int r = 0; r < RR; ++r) s += qb[e * RR + r] * qa[r * DD + d];
        w += LORA_SCALE * s;
    } else if (e >= 2 * DD) {
        int eb = e - 2 * DD;
        float s = 0.f;
#pragma unroll
        for (int r = 0; r < RR; ++r) s += vb[eb * RR + r] * va[r * DD + d];
        w += LORA_SCALE * s;
    }
    weff[idx] = rnd_tf32(w);
}

// -------------------- 3/6) TF32 GEMM: 4 warps, 64x64 warp tile (R13 exact) ------
#define BM 128
#define BN 128
#define BK 16
#define SKW (BK + 8)   // 24
#define GSTG 3
#define SMEM_GEMM (GSTG * 2 * BM * SKW * 4)   // 73728 bytes

#define AS(s, r, c) sm_a[((s) * BM + (r)) * SKW + (c)]
#define WS(s, r, c) sm_w[((s) * BN + (r)) * SKW + (c)]

__global__ void __launch_bounds__(128, 2) gemm_tf32(const float* __restrict__ A,
                                                    const float* __restrict__ W,
                                                    float* __restrict__ C,
                                                    int M, int N, int K) {
    extern __shared__ uint32_t sm[];
    uint32_t* sm_a = sm;
    uint32_t* sm_w = sm + GSTG * BM * SKW;

    const int tid = threadIdx.x;
    const int lane = tid & 31;
    const int wid = tid >> 5;               // 0..3
    const int g = lane >> 2, tg = lane & 3;
    const int wm = wid >> 1, wn = wid & 1;  // 2 x 2 warp grid, 64x64 warp tile
    const int bm = blockIdx.y * BM, bn = blockIdx.x * BN;

    int row_[4], kc_[4];
#pragma unroll
    for (int l = 0; l < 4; ++l) {
        int idx = tid + l * 128;
        row_[l] = idx >> 2;
        kc_[l] = (idx & 3) << 2;
    }

    const float* gA = A + (size_t)bm * K;
    const float* gW = W + (size_t)bn * K;

    auto issue = [&](int s, int t) {
#pragma unroll
        for (int l = 0; l < 4; ++l) {
            uint32_t sa = (uint32_t)__cvta_generic_to_shared(&AS(s, row_[l], kc_[l]));
            cp_async16(sa, gA + (size_t)row_[l] * K + t * BK + kc_[l]);
            uint32_t sw = (uint32_t)__cvta_generic_to_shared(&WS(s, row_[l], kc_[l]));
            cp_async16(sw, gW + (size_t)row_[l] * K + t * BK + kc_[l]);
        }
        cp_commit();
    };

    const int nk = K / BK;
    issue(0, 0);
    issue(1, 1);

    float c[4][8][4] = {};

    for (int t = 0; t < nk; ++t) {
        if (t + 2 < nk) cp_wait<1>(); else cp_wait<0>();
        __syncthreads();
        if (t + 2 < nk) issue((t + 2) % GSTG, t + 2);

        const int buf = t % GSTG;
#pragma unroll
        for (int ks = 0; ks < BK; ks += 8) {
            uint32_t af[4][4], bf[8][2];
#pragma unroll
            for (int mt = 0; mt < 4; ++mt) {
                int m = wm * 64 + mt * 16;
                uint2 a0 = *reinterpret_cast<const uint2*>(&AS(buf, m + g,     ks + 2 * tg));
                uint2 a1 = *reinterpret_cast<const uint2*>(&AS(buf, m + g + 8, ks + 2 * tg));
                af[mt][0] = a0.x; af[mt][2] = a0.y;
                af[mt][1] = a1.x; af[mt][3] = a1.y;
            }
#pragma unroll
            for (int nt = 0; nt < 8; ++nt) {
                int n = wn * 64 + nt * 8;
                uint2 b0 = *reinterpret_cast<const uint2*>(&WS(buf, n + g, ks + 2 * tg));
                bf[nt][0] = b0.x; bf[nt][1] = b0.y;
            }
#pragma unroll
            for (int mt = 0; mt < 4; ++mt)
#pragma unroll
                for (int nt = 0; nt < 8; ++nt)
                    mma_tf32(c[mt][nt], af[mt], bf[nt]);
        }
    }

#pragma unroll
    for (int mt = 0; mt < 4; ++mt) {
        int row0 = bm + wm * 64 + mt * 16 + g;
#pragma unroll
        for (int nt = 0; nt < 8; ++nt) {
            int col = bn + wn * 64 + nt * 8 + 2 * tg;
            *reinterpret_cast<float2*>(C + (size_t)row0 * N + col) =
                make_float2(c[mt][nt][0], c[mt][nt][1]);
            *reinterpret_cast<float2*>(C + (size_t)(row0 + 8) * N + col) =
                make_float2(c[mt][nt][2], c[mt][nt][3]);
        }
    }
}

// -------------------- 4) q/k LN + RoPE + head transpose --------------------
__global__ void transform_kernel(const float* __restrict__ qkv,
                                 const float* __restrict__ qw, const float* __restrict__ kw,
                                 const float* __restrict__ rcos, const float* __restrict__ rsin,
                                 float* __restrict__ gq, float* __restrict__ gk,
                                 float* __restrict__ gv) {
    __shared__ float sq[DD];
    __shared__ float sk[DD];
    __shared__ float4 buf[8];
    int n = blockIdx.x;
    int b = n >> 11, l = n & 2047;
    int tid = threadIdx.x;
    const float* row = qkv + (size_t)n * (3 * DD);
    float4 qv = reinterpret_cast<const float4*>(row)[tid];
    float4 kv = reinterpret_cast<const float4*>(row + DD)[tid];
    float4 vv = reinterpret_cast<const float4*>(row + 2 * DD)[tid];

    {
        int d = tid * 4;
        int h = d >> 6, j = d & 63;
        float* dst = gv + ((((size_t)b * HH + h) * LL + l) * DHD + j);
        *reinterpret_cast<float4*>(dst) = vv;
    }

    float4 sums = make_float4(qv.x + qv.y + qv.z + qv.w,
                              qv.x * qv.x + qv.y * qv.y + qv.z * qv.z + qv.w * qv.w,
                              kv.x + kv.y + kv.z + kv.w,
                              kv.x * kv.x + kv.y * kv.y + kv.z * kv.z + kv.w * kv.w);
    float4 r = block_reduce4(sums, buf);
    float muq = r.x * (1.f / DD), ivq = rsqrtf(r.y * (1.f / DD) - muq * muq + 1e-5f);
    float muk = r.z * (1.f / DD), ivk = rsqrtf(r.w * (1.f / DD) - muk * muk + 1e-5f);
    float4 qwv = reinterpret_cast<const float4*>(qw)[tid];
    float4 kwv = reinterpret_cast<const float4*>(kw)[tid];
    int d0 = tid * 4;
    sq[d0 + 0] = (qv.x - muq) * ivq * qwv.x;
    sq[d0 + 1] = (qv.y - muq) * ivq * qwv.y;
    sq[d0 + 2] = (qv.z - muq) * ivq * qwv.z;
    sq[d0 + 3] = (qv.w - muq) * ivq * qwv.w;
    sk[d0 + 0] = (kv.x - muk) * ivk * kwv.x;
    sk[d0 + 1] = (kv.y - muk) * ivk * kwv.y;
    sk[d0 + 2] = (kv.z - muk) * ivk * kwv.z;
    sk[d0 + 3] = (kv.w - muk) * ivk * kwv.w;
    __syncthreads();

    float oq[4], ok[4];
#pragma unroll
    for (int c = 0; c < 4; ++c) {
        int d = d0 + c;
        int j = d & 63;
        int jj = j & 31;
        float cs = rcos[l * 32 + jj];
        float sn = rsin[l * 32 + jj];
        if (j < 32) {
            oq[c] = sq[d] * cs - sq[d + 32] * sn;
            ok[c] = sk[d] * cs - sk[d + 32] * sn;
        } else {
            oq[c] = sq[d] * cs + sq[d - 32] * sn;
            ok[c] = sk[d] * cs + sk[d - 32] * sn;
        }
    }
    int h = d0 >> 6, j = d0 & 63;
    size_t base = (((size_t)b * HH + h) * LL + l) * DHD + j;
    *reinterpret_cast<float4*>(gq + base) = make_float4(oq[0], oq[1], oq[2], oq[3]);
    *reinterpret_cast<float4*>(gk + base) = make_float4(ok[0], ok[1], ok[2], ok[3]);
}

// -------------------- 5) flash attention: KT=64, S = 3xTF32, PV = plain TF32 --------
#define QT 64
#define KT2 64
#define APAD 72
// dynamic smem (uint32): Khi[64][72] | Klo[64][72] | Vth[64][72]
#define AT_KHI 0
#define AT_KLO (64 * APAD)
#define AT_VTH (2 * 64 * APAD)
#define ATSMEM (3 * 64 * APAD * 4)   // 55296 bytes

__device__ __forceinline__ int perm_k(int d) {
    return 8 * (d >> 3) + 2 * (d & 3) + ((d >> 2) & 1);
}

__global__ void __launch_bounds__(128) attn_tc_kernel(const float* __restrict__ gq,
                                                      const float* __restrict__ gk,
                                                      const float* __restrict__ gv,
                                                      const int* __restrict__ seq_id,
                                                      float* __restrict__ ctx) {
    extern __shared__ uint32_t smu[];
    uint32_t* Khi = smu + AT_KHI;   // [64][APAD]
    uint32_t* Klo = smu + AT_KLO;
    uint32_t* Vth = smu + AT_VTH;   // [DHD][APAD] (keys along row)
    __shared__ int sk_s[KT2];

    const int q0 = blockIdx.x * QT;
    const int h = blockIdx.y;
    const int b = blockIdx.z;
    const float* qbase = gq + (((size_t)b * HH + h) * LL) * DHD;
    const float* kbase = gk + (((size_t)b * HH + h) * LL) * DHD;
    const float* vbase = gv + (((size_t)b * HH + h) * LL) * DHD;
    const int* sid = seq_id + (size_t)b * LL;

    const int tid = threadIdx.x;
    const int lane = tid & 31;
    const int wid = tid >> 5;
    const int g = lane >> 2, tg = lane & 3;
    const int wrow = wid * 16;

    // ---- Q fragments (row-scaled, split hi/lo), in registers ----
    uint32_t qhi[8][4], qlo[8][4];
    {
        const float* r0 = qbase + (size_t)(q0 + wrow + g) * DHD;
        const float* r1 = qbase + (size_t)(q0 + wrow + g + 8) * DHD;
#pragma unroll
        for (int ks = 0; ks < 8; ++ks) {
            float f[4];
            f[0] = r0[ks * 8 + tg]     * ATTN_SCALE;
            f[1] = r1[ks * 8 + tg]     * ATTN_SCALE;
            f[2] = r0[ks * 8 + tg + 4] * ATTN_SCALE;
            f[3] = r1[ks * 8 + tg + 4] * ATTN_SCALE;
#pragma unroll
            for (int j = 0; j < 4; ++j) {
                uint32_t hi = f2tf32(f[j]);
                qhi[ks][j] = hi;
                qlo[ks][j] = f2tf32(f[j] - __uint_as_float(hi));
            }
        }
    }

    const int sqr0 = sid[q0 + wrow + g];
    const int sqr1 = sid[q0 + wrow + g + 8];
    const int sqmin = sid[q0], sqmax = sid[q0 + QT - 1];

    float o[8][4] = {};
    float m0 = -1e30f, m1 = -1e30f, l0 = 0.f, l1 = 0.f;

    for (int k0 = 0; k0 < LL; k0 += KT2) {
        int kmin = sid[k0], kmax = sid[k0 + KT2 - 1];
        if (kmax < sqmin || kmin > sqmax) continue;

        __syncthreads();

        // ---- K tile 64x64: 3x split (hi/lo), d-permuted ----
#pragma unroll
        for (int it = 0; it < 8; ++it) {
            int idx = tid + it * 128;       // 0..1023 float4s
            int ki = idx >> 4;              // 0..63
            int dc = (idx & 15) << 2;
            float4 v = *reinterpret_cast<const float4*>(kbase + (size_t)(k0 + ki) * DHD + dc);
            float f[4] = {v.x, v.y, v.z, v.w};
#pragma unroll
            for (int j = 0; j < 4; ++j) {
                int p = perm_k(dc + j);
                uint32_t hi = f2tf32(f[j]);
                Khi[ki * APAD + p] = hi;
                Klo[ki * APAD + p] = f2tf32(f[j] - __uint_as_float(hi));
            }
        }
        // ---- V tile 64x64: plain tf32, transposed, k-permuted ----
#pragma unroll
        for (int it = 0; it < 8; ++it) {
            int idx = tid + it * 128;       // 0..1023 float4s
            int ki = idx & 63;
            int dc = ((idx >> 6) & 15) << 2;
            int pk = perm_k(ki);
            float4 v = *reinterpret_cast<const float4*>(vbase + (size_t)(k0 + ki) * DHD + dc);
            Vth[(dc + 0) * APAD + pk] = f2tf32(v.x);
            Vth[(dc + 1) * APAD + pk] = f2tf32(v.y);
            Vth[(dc + 2) * APAD + pk] = f2tf32(v.z);
            Vth[(dc + 3) * APAD + pk] = f2tf32(v.w);
        }
        if (tid < KT2) sk_s[tid] = sid[k0 + tid];
        __syncthreads();

        // ---- S = Q K^T (3xTF32), 8 n-chunks ----
        float s[8][4] = {};
#pragma unroll
        for (int ks = 0; ks < 8; ++ks) {
#pragma unroll
            for (int nt = 0; nt < 8; ++nt) {
                uint2 bh2 = *reinterpret_cast<const uint2*>(&Khi[(nt * 8 + g) * APAD + 8 * ks + 2 * tg]);
                uint2 bl2 = *reinterpret_cast<const uint2*>(&Klo[(nt * 8 + g) * APAD + 8 * ks + 2 * tg]);
                uint32_t bh[2] = {bh2.x, bh2.y};
                uint32_t bl[2] = {bl2.x, bl2.y};
                mma_tf32(s[nt], qhi[ks], bh);
                mma_tf32(s[nt], qlo[ks], bh);
                mma_tf32(s[nt], qhi[ks], bl);
            }
        }

        // ---- mask ----
#pragma unroll
        for (int nt = 0; nt < 8; ++nt) {
            int c = nt * 8 + 2 * tg;
            int sk0 = sk_s[c], sk1 = sk_s[c + 1];
            if (sqr0 != sk0) s[nt][0] = -1e30f;
            if (sqr0 != sk1) s[nt][1] = -1e30f;
            if (sqr1 != sk0) s[nt][2] = -1e30f;
            if (sqr1 != sk1) s[nt][3] = -1e30f;
        }

        // ---- online softmax over 64 keys ----
        float mx0 = -1e30f, mx1 = -1e30f;
#pragma unroll
        for (int nt = 0; nt < 8; ++nt) {
            mx0 = fmaxf(mx0, fmaxf(s[nt][0], s[nt][1]));
            mx1 = fmaxf(mx1, fmaxf(s[nt][2], s[nt][3]));
        }
        mx0 = fmaxf(mx0, __shfl_xor_sync(0xffffffffu, mx0, 1));
        mx0 = fmaxf(mx0, __shfl_xor_sync(0xffffffffu, mx0, 2));
        mx1 = fmaxf(mx1, __shfl_xor_sync(0xffffffffu, mx1, 1));
        mx1 = fmaxf(mx1, __shfl_xor_sync(0xffffffffu, mx1, 2));
        float mn0 = fmaxf(m0, mx0), mn1 = fmaxf(m1, mx1);
        float al0 = __expf(m0 - mn0), al1 = __expf(m1 - mn1);
        float ps0 = 0.f, ps1 = 0.f;
#pragma unroll
        for (int nt = 0; nt < 8; ++nt) {
            float p00 = (s[nt][0] < -1e29f) ? 0.f : __expf(s[nt][0] - mn0);
            float p01 = (s[nt][1] < -1e29f) ? 0.f : __expf(s[nt][1] - mn0);
            float p10 = (s[nt][2] < -1e29f) ? 0.f : __expf(s[nt][2] - mn1);
            float p11 = (s[nt][3] < -1e29f) ? 0.f : __expf(s[nt][3] - mn1);
            s[nt][0] = p00; s[nt][1] = p01; s[nt][2] = p10; s[nt][3] = p11;
            ps0 += p00 + p01;
            ps1 += p10 + p11;
        }
        ps0 += __shfl_xor_sync(0xffffffffu, ps0, 1);
        ps0 += __shfl_xor_sync(0xffffffffu, ps0, 2);
        ps1 += __shfl_xor_sync(0xffffffffu, ps1, 1);
        ps1 += __shfl_xor_sync(0xffffffffu, ps1, 2);
        l0 = l0 * al0 + ps0;
        l1 = l1 * al1 + ps1;
        m0 = mn0; m1 = mn1;

#pragma unroll
        for (int dt = 0; dt < 8; ++dt) {
            o[dt][0] *= al0; o[dt][1] *= al0;
            o[dt][2] *= al1; o[dt][3] *= al1;
        }

        // ---- O += P V (plain TF32) ----
#pragma unroll
        for (int nt = 0; nt < 8; ++nt) {
            int s0l = (lane & ~3) | (tg >> 1);
            int s1l = s0l + 2;
            float e0 = __shfl_sync(0xffffffffu, s[nt][0], s0l);
            float e1 = __shfl_sync(0xffffffffu, s[nt][1], s0l);
            float e2 = __shfl_sync(0xffffffffu, s[nt][2], s0l);
            float e3 = __shfl_sync(0xffffffffu, s[nt][3], s0l);
            float f0 = __shfl_sync(0xffffffffu, s[nt][0], s1l);
            float f1 = __shfl_sync(0xffffffffu, s[nt][1], s1l);
            float f2 = __shfl_sync(0xffffffffu, s[nt][2], s1l);
            float f3 = __shfl_sync(0xffffffffu, s[nt][3], s1l);
            bool odd = (tg & 1);
            float a0f = odd ? e1 : e0;
            float a1f = odd ? e3 : e2;
            float a2f = odd ? f1 : f0;
            float a3f = odd ? f3 : f2;
            uint32_t ah[4];
            ah[0] = f2tf32(a0f);
            ah[1] = f2tf32(a1f);
            ah[2] = f2tf32(a2f);
            ah[3] = f2tf32(a3f);
#pragma unroll
            for (int dt = 0; dt < 8; ++dt) {
                uint2 vh2 = *reinterpret_cast<const uint2*>(&Vth[(dt * 8 + g) * APAD + 8 * nt + 2 * tg]);
                uint32_t bh[2] = {vh2.x, vh2.y};
                mma_tf32(o[dt], ah, bh);
            }
        }
    }

    // epilogue: pre-round ctx to tf32 grid (feeds the raw-bit out-proj GEMM)
    float invl0 = 1.f / l0, invl1 = 1.f / l1;
    size_t row0 = ((size_t)b * LL + q0 + wrow + g) * DD + h * DHD;
    size_t row1 = ((size_t)b * LL + q0 + wrow + g + 8) * DD + h * DHD;
#pragma unroll
    for (int dt = 0; dt < 8; ++dt) {
        int col = dt * 8 + 2 * tg;
        *reinterpret_cast<float2*>(ctx + row0 + col) =
            make_float2(rnd_tf32(o[dt][0] * invl0), rnd_tf32(o[dt][1] * invl0));
        *reinterpret_cast<float2*>(ctx + row1 + col) =
            make_float2(rnd_tf32(o[dt][2] * invl1), rnd_tf32(o[dt][3] * invl1));
    }
}

// -------------------- launch --------------------
extern "C" void kernel_launch(void* const* d_in, const int* in_sizes, int n_in,
                              void* d_out, int out_size) {
    const float* x      = (const float*)d_in[0];
    const int*   seq    = (const int*)  d_in[1];
    const float* ln_w   = (const float*)d_in[2];
    const float* ln_b   = (const float*)d_in[3];
    const float* w_qkv  = (const float*)d_in[4];
    const float* qa     = (const float*)d_in[5];
    const float* qb     = (const float*)d_in[6];
    const float* va     = (const float*)d_in[7];
    const float* vb     = (const float*)d_in[8];
    const float* q_ln_w = (const float*)d_in[9];
    const float* k_ln_w = (const float*)d_in[10];
    const float* w_out  = (const float*)d_in[11];
    float* out = (float*)d_out;

    float *ph, *pweff, *pqkv, *pq, *pk, *pv, *pctx, *prc, *prs, *pwo;
    cudaGetSymbolAddress((void**)&ph,    g_h);
    cudaGetSymbolAddress((void**)&pweff, g_weff);
    cudaGetSymbolAddress((void**)&pqkv,  g_qkv);
    cudaGetSymbolAddress((void**)&pq,    g_q);
    cudaGetSymbolAddress((void**)&pk,    g_k);
    cudaGetSymbolAddress((void**)&pv,    g_v);
    cudaGetSymbolAddress((void**)&pctx,  g_ctx);
    cudaGetSymbolAddress((void**)&prc,   g_rcos);
    cudaGetSymbolAddress((void**)&prs,   g_rsin);
    cudaGetSymbolAddress((void**)&pwo,   g_wout_r);

    cudaFuncSetAttribute(gemm_tf32, cudaFuncAttributeMaxDynamicSharedMemorySize, SMEM_GEMM);
    cudaFuncSetAttribute(attn_tc_kernel, cudaFuncAttributeMaxDynamicSharedMemorySize, ATSMEM);

    rope_table_kernel<<<(LL * 32 + 255) / 256, 256>>>(prc, prs);
    ln_kernel<<<NROWS, 256>>>(x, ln_w, ln_b, ph);
    weff_kernel<<<(4 * DD * DD + 255) / 256, 256>>>(w_qkv, qa, qb, va, vb, w_out, pwo, pweff);
    gemm_tf32<<<dim3(3 * DD / BN, NROWS / BM), 128, SMEM_GEMM>>>(ph, pweff, pqkv, NROWS, 3 * DD, DD);
    transform_kernel<<<NROWS, 256>>>(pqkv, q_ln_w, k_ln_w, prc, prs, pq, pk, pv);
    attn_tc_kernel<<<dim3(LL / QT, HH, BB), 128, ATSMEM>>>(pq, pk, pv, seq, pctx);
    gemm_tf32<<<dim3(DD / BN, NROWS / BM), 128, SMEM_GEMM>>>(pctx, pwo, out, NROWS, DD, DD);
}

// round 16
// speedup vs baseline: 1.4254x; 1.1525x over previous
#include <cuda_runtime.h>
#include <cuda_bf16.h>
#include <math.h>
#include <stddef.h>
#include <stdint.h>

// Problem constants
#define BB 2
#define LL 2048
#define DD 1024
#define HH 16
#define DHD 64
#define RR 32
#define NROWS (BB*LL)          // 4096
#define LORA_SCALE 2.0f
#define ATTN_SCALE 0.125f      // 1/sqrt(64)

// -------------------- scratch (static device memory, allowed) --------------------
__device__ float g_h[NROWS * DD];          // tf32-rounded LN(x)
__device__ float g_weff[3 * DD * DD];      // tf32-rounded qkv weight + lora
__device__ float g_qkv[NROWS * 3 * DD];
__device__ float g_q[BB * HH * LL * DHD];  // [B,H,L,DH]
__device__ uint32_t g_khp[BB * HH * LL * 32];  // [B,H,L,perm(pair)] bf16x2 hi of rope'd k
__device__ uint32_t g_klp[BB * HH * LL * 32];  // bf16x2 lo
__device__ float g_v[BB * HH * LL * DHD];
__device__ float g_ctx[NROWS * DD];        // tf32-rounded attention output
__device__ float g_rcos[LL * 32];
__device__ float g_rsin[LL * 32];
__device__ float g_wout_r[DD * DD];        // tf32-rounded w_out

// -------------------- helpers --------------------
__device__ __forceinline__ uint32_t f2tf32(float f) {
    uint32_t r;
    asm("cvt.rna.tf32.f32 %0, %1;" : "=r"(r) : "f"(f));
    return r;
}
__device__ __forceinline__ float rnd_tf32(float f) {
    return __uint_as_float(f2tf32(f));
}
__device__ __forceinline__ uint32_t packbf(float lo, float hi) {
    __nv_bfloat162 p = __floats2bfloat162_rn(lo, hi);   // x (=lo elem) in low 16 bits
    return *reinterpret_cast<uint32_t*>(&p);
}
__device__ __forceinline__ float bfh(float x) {         // bf16-rounded value
    return __bfloat162float(__float2bfloat16_rn(x));
}

__device__ __forceinline__ void mma_tf32(float* c, const uint32_t* a, const uint32_t* b) {
    asm volatile(
        "mma.sync.aligned.m16n8k8.row.col.f32.tf32.tf32.f32 "
        "{%0,%1,%2,%3}, {%4,%5,%6,%7}, {%8,%9}, {%0,%1,%2,%3};\n"
        : "+f"(c[0]), "+f"(c[1]), "+f"(c[2]), "+f"(c[3])
        : "r"(a[0]), "r"(a[1]), "r"(a[2]), "r"(a[3]), "r"(b[0]), "r"(b[1]));
}

__device__ __forceinline__ void mma_bf16(float* c, const uint32_t* a, const uint32_t* b) {
    asm volatile(
        "mma.sync.aligned.m16n8k16.row.col.f32.bf16.bf16.f32 "
        "{%0,%1,%2,%3}, {%4,%5,%6,%7}, {%8,%9}, {%0,%1,%2,%3};\n"
        : "+f"(c[0]), "+f"(c[1]), "+f"(c[2]), "+f"(c[3])
        : "r"(a[0]), "r"(a[1]), "r"(a[2]), "r"(a[3]), "r"(b[0]), "r"(b[1]));
}

__device__ __forceinline__ void cp_async16(uint32_t saddr, const void* gptr) {
    asm volatile("cp.async.ca.shared.global [%0], [%1], 16;\n" :: "r"(saddr), "l"(gptr));
}
__device__ __forceinline__ void cp_commit() {
    asm volatile("cp.async.commit_group;\n");
}
template<int N>
__device__ __forceinline__ void cp_wait() {
    asm volatile("cp.async.wait_group %0;\n" :: "n"(N));
}

__device__ __forceinline__ float4 block_reduce4(float4 v, float4* buf) {
#pragma unroll
    for (int o = 16; o; o >>= 1) {
        v.x += __shfl_xor_sync(0xffffffffu, v.x, o);
        v.y += __shfl_xor_sync(0xffffffffu, v.y, o);
        v.z += __shfl_xor_sync(0xffffffffu, v.z, o);
        v.w += __shfl_xor_sync(0xffffffffu, v.w, o);
    }
    int w = threadIdx.x >> 5, lane = threadIdx.x & 31;
    if (lane == 0) buf[w] = v;
    __syncthreads();
    if (w == 0) {
        v = (lane < 8) ? buf[lane] : make_float4(0.f, 0.f, 0.f, 0.f);
#pragma unroll
        for (int o = 4; o; o >>= 1) {
            v.x += __shfl_xor_sync(0xffffffffu, v.x, o);
            v.y += __shfl_xor_sync(0xffffffffu, v.y, o);
            v.z += __shfl_xor_sync(0xffffffffu, v.z, o);
            v.w += __shfl_xor_sync(0xffffffffu, v.w, o);
        }
        if (lane == 0) buf[0] = v;
    }
    __syncthreads();
    return buf[0];
}

// -------------------- 0) RoPE table --------------------
__global__ void rope_table_kernel(float* __restrict__ rc, float* __restrict__ rs) {
    int i = blockIdx.x * blockDim.x + threadIdx.x;
    if (i >= LL * 32) return;
    int l = i >> 5, jj = i & 31;
    double invf = exp(-0.28782313662425575 * (double)jj);
    double ang = (double)l * invf;
    double sd, cd;
    sincos(ang, &sd, &cd);
    rc[i] = (float)cd;
    rs[i] = (float)sd;
}

// -------------------- 1) input LayerNorm (pre-rounded output) --------------------
__global__ void ln_kernel(const float* __restrict__ x, const float* __restrict__ w,
                          const float* __restrict__ b, float* __restrict__ out) {
    __shared__ float4 buf[8];
    int n = blockIdx.x;
    int tid = threadIdx.x;
    const float4* xr = reinterpret_cast<const float4*>(x + (size_t)n * DD);
    float4 xv = xr[tid];
    float4 sums = make_float4(xv.x + xv.y + xv.z + xv.w,
                              xv.x * xv.x + xv.y * xv.y + xv.z * xv.z + xv.w * xv.w,
                              0.f, 0.f);
    float4 r = block_reduce4(sums, buf);
    float mu = r.x * (1.f / DD);
    float var = r.y * (1.f / DD) - mu * mu;
    float inv = rsqrtf(var + 1e-5f);
    float4 wv = reinterpret_cast<const float4*>(w)[tid];
    float4 bv = reinterpret_cast<const float4*>(b)[tid];
    float4 o;
    o.x = rnd_tf32((xv.x - mu) * inv * wv.x + bv.x);
    o.y = rnd_tf32((xv.y - mu) * inv * wv.y + bv.y);
    o.z = rnd_tf32((xv.z - mu) * inv * wv.z + bv.z);
    o.w = rnd_tf32((xv.w - mu) * inv * wv.w + bv.w);
    reinterpret_cast<float4*>(out + (size_t)n * DD)[tid] = o;
}

// -------------------- 2) fold LoRA into QKV weight + round w_out (fused) ----------
__global__ void weff_kernel(const float* __restrict__ wqkv,
                            const float* __restrict__ qa, const float* __restrict__ qb,
                            const float* __restrict__ va, const float* __restrict__ vb,
                            const float* __restrict__ wout, float* __restrict__ woutr,
                            float* __restrict__ weff) {
    int idx = blockIdx.x * blockDim.x + threadIdx.x;
    if (idx >= 4 * DD * DD) return;
    if (idx >= 3 * DD * DD) {
        int i = idx - 3 * DD * DD;
        woutr[i] = rnd_tf32(wout[i]);
        return;
    }
    int e = idx >> 10, d = idx & 1023;
    float w = wqkv[idx];
    if (e < DD) {
        float s = 0.f;
#pragma unroll
        for (int r = 0; r < RR; ++r) s += qb[e * RR + r] * qa[r * DD + d];
        w += LORA_SCALE * s;
    } else if (e >= 2 * DD) {
        int eb = e - 2 * DD;
        float s = 0.f;
#pragma unroll
        for (int r = 0; r < RR; ++r) s += vb[eb * RR + r] * va[r * DD + d];
        w += LORA_SCALE * s;
    }
    weff[idx] = rnd_tf32(w);
}

// -------------------- 3/6) TF32 GEMM: 4 warps, 64x64 warp tile (R13 exact) ------
#define BM 128
#define BN 128
#define BK 16
#define SKW (BK + 8)   // 24
#define GSTG 3
#define SMEM_GEMM (GSTG * 2 * BM * SKW * 4)   // 73728 bytes

#define AS(s, r, c) sm_a[((s) * BM + (r)) * SKW + (c)]
#define WS(s, r, c) sm_w[((s) * BN + (r)) * SKW + (c)]

__global__ void __launch_bounds__(128, 2) gemm_tf32(const float* __restrict__ A,
                                                    const float* __restrict__ W,
                                                    float* __restrict__ C,
                                                    int M, int N, int K) {
    extern __shared__ uint32_t sm[];
    uint32_t* sm_a = sm;
    uint32_t* sm_w = sm + GSTG * BM * SKW;

    const int tid = threadIdx.x;
    const int lane = tid & 31;
    const int wid = tid >> 5;
    const int g = lane >> 2, tg = lane & 3;
    const int wm = wid >> 1, wn = wid & 1;
    const int bm = blockIdx.y * BM, bn = blockIdx.x * BN;

    int row_[4], kc_[4];
#pragma unroll
    for (int l = 0; l < 4; ++l) {
        int idx = tid + l * 128;
        row_[l] = idx >> 2;
        kc_[l] = (idx & 3) << 2;
    }

    const float* gA = A + (size_t)bm * K;
    const float* gW = W + (size_t)bn * K;

    auto issue = [&](int s, int t) {
#pragma unroll
        for (int l = 0; l < 4; ++l) {
            uint32_t sa = (uint32_t)__cvta_generic_to_shared(&AS(s, row_[l], kc_[l]));
            cp_async16(sa, gA + (size_t)row_[l] * K + t * BK + kc_[l]);
            uint32_t sw = (uint32_t)__cvta_generic_to_shared(&WS(s, row_[l], kc_[l]));
            cp_async16(sw, gW + (size_t)row_[l] * K + t * BK + kc_[l]);
        }
        cp_commit();
    };

    const int nk = K / BK;
    issue(0, 0);
    issue(1, 1);

    float c[4][8][4] = {};

    for (int t = 0; t < nk; ++t) {
        if (t + 2 < nk) cp_wait<1>(); else cp_wait<0>();
        __syncthreads();
        if (t + 2 < nk) issue((t + 2) % GSTG, t + 2);

        const int buf = t % GSTG;
#pragma unroll
        for (int ks = 0; ks < BK; ks += 8) {
            uint32_t af[4][4], bf[8][2];
#pragma unroll
            for (int mt = 0; mt < 4; ++mt) {
                int m = wm * 64 + mt * 16;
                uint2 a0 = *reinterpret_cast<const uint2*>(&AS(buf, m + g,     ks + 2 * tg));
                uint2 a1 = *reinterpret_cast<const uint2*>(&AS(buf, m + g + 8, ks + 2 * tg));
                af[mt][0] = a0.x; af[mt][2] = a0.y;
                af[mt][1] = a1.x; af[mt][3] = a1.y;
            }
#pragma unroll
            for (int nt = 0; nt < 8; ++nt) {
                int n = wn * 64 + nt * 8;
                uint2 b0 = *reinterpret_cast<const uint2*>(&WS(buf, n + g, ks + 2 * tg));
                bf[nt][0] = b0.x; bf[nt][1] = b0.y;
            }
#pragma unroll
            for (int mt = 0; mt < 4; ++mt)
#pragma unroll
                for (int nt = 0; nt < 8; ++nt)
                    mma_tf32(c[mt][nt], af[mt], bf[nt]);
        }
    }

#pragma unroll
    for (int mt = 0; mt < 4; ++mt) {
        int row0 = bm + wm * 64 + mt * 16 + g;
#pragma unroll
        for (int nt = 0; nt < 8; ++nt) {
            int col = bn + wn * 64 + nt * 8 + 2 * tg;
            *reinterpret_cast<float2*>(C + (size_t)row0 * N + col) =
                make_float2(c[mt][nt][0], c[mt][nt][1]);
            *reinterpret_cast<float2*>(C + (size_t)(row0 + 8) * N + col) =
                make_float2(c[mt][nt][2], c[mt][nt][3]);
        }
    }
}

// -------------------- pair-index perm (8-blockwise), for K bf16 pairs & V keys ------
__device__ __forceinline__ int perm_k(int d) {
    return (d & ~7) + 2 * (d & 3) + ((d >> 2) & 1);
}

// -------------------- 4) q/k LN + RoPE; k -> packed bf16 hi/lo, perm'd -------------
__global__ void transform_kernel(const float* __restrict__ qkv,
                                 const float* __restrict__ qw, const float* __restrict__ kw,
                                 const float* __restrict__ rcos, const float* __restrict__ rsin,
                                 float* __restrict__ gq,
                                 uint32_t* __restrict__ gkhp, uint32_t* __restrict__ gklp,
                                 float* __restrict__ gv) {
    __shared__ float sq[DD];
    __shared__ float sk[DD];
    __shared__ float4 buf[8];
    int n = blockIdx.x;
    int b = n >> 11, l = n & 2047;
    int tid = threadIdx.x;
    const float* row = qkv + (size_t)n * (3 * DD);
    float4 qv = reinterpret_cast<const float4*>(row)[tid];
    float4 kv = reinterpret_cast<const float4*>(row + DD)[tid];
    float4 vv = reinterpret_cast<const float4*>(row + 2 * DD)[tid];

    {
        int d = tid * 4;
        int h = d >> 6, j = d & 63;
        float* dst = gv + ((((size_t)b * HH + h) * LL + l) * DHD + j);
        *reinterpret_cast<float4*>(dst) = vv;
    }

    float4 sums = make_float4(qv.x + qv.y + qv.z + qv.w,
                              qv.x * qv.x + qv.y * qv.y + qv.z * qv.z + qv.w * qv.w,
                              kv.x + kv.y + kv.z + kv.w,
                              kv.x * kv.x + kv.y * kv.y + kv.z * kv.z + kv.w * kv.w);
    float4 r = block_reduce4(sums, buf);
    float muq = r.x * (1.f / DD), ivq = rsqrtf(r.y * (1.f / DD) - muq * muq + 1e-5f);
    float muk = r.z * (1.f / DD), ivk = rsqrtf(r.w * (1.f / DD) - muk * muk + 1e-5f);
    float4 qwv = reinterpret_cast<const float4*>(qw)[tid];
    float4 kwv = reinterpret_cast<const float4*>(kw)[tid];
    int d0 = tid * 4;
    sq[d0 + 0] = (qv.x - muq) * ivq * qwv.x;
    sq[d0 + 1] = (qv.y - muq) * ivq * qwv.y;
    sq[d0 + 2] = (qv.z - muq) * ivq * qwv.z;
    sq[d0 + 3] = (qv.w - muq) * ivq * qwv.w;
    sk[d0 + 0] = (kv.x - muk) * ivk * kwv.x;
    sk[d0 + 1] = (kv.y - muk) * ivk * kwv.y;
    sk[d0 + 2] = (kv.z - muk) * ivk * kwv.z;
    sk[d0 + 3] = (kv.w - muk) * ivk * kwv.w;
    __syncthreads();

    float oq[4], ok[4];
#pragma unroll
    for (int c = 0; c < 4; ++c) {
        int d = d0 + c;
        int j = d & 63;
        int jj = j & 31;
        float cs = rcos[l * 32 + jj];
        float sn = rsin[l * 32 + jj];
        if (j < 32) {
            oq[c] = sq[d] * cs - sq[d + 32] * sn;
            ok[c] = sk[d] * cs - sk[d + 32] * sn;
        } else {
            oq[c] = sq[d] * cs + sq[d - 32] * sn;
            ok[c] = sk[d] * cs + sk[d - 32] * sn;
        }
    }
    int h = d0 >> 6, j0 = d0 & 63;
    size_t qb_ = (((size_t)b * HH + h) * LL + l) * DHD + j0;
    *reinterpret_cast<float4*>(gq + qb_) = make_float4(oq[0], oq[1], oq[2], oq[3]);

    // k: bf16 hi/lo split, packed in pairs along d, pair-index perm'd
    size_t kb_ = (((size_t)b * HH + h) * LL + l) * 32;
    int jp = (j0 >> 1);                    // pair index of first pair (even)
    float h0 = bfh(ok[0]), h1 = bfh(ok[1]), h2 = bfh(ok[2]), h3 = bfh(ok[3]);
    gkhp[kb_ + perm_k(jp)]     = packbf(h0, h1);
    gkhp[kb_ + perm_k(jp + 1)] = packbf(h2, h3);
    float l0v = bfh(ok[0] - h0), l1v = bfh(ok[1] - h1);
    float l2v = bfh(ok[2] - h2), l3v = bfh(ok[3] - h3);
    gklp[kb_ + perm_k(jp)]     = packbf(l0v, l1v);
    gklp[kb_ + perm_k(jp + 1)] = packbf(l2v, l3v);
}

// -------------------- 5) flash attention: S = 3x bf16 m16n8k16, PV = tf32 ----------
#define QT 64
#define KT2 64
#define KP2 40    // K pair-row stride (32+8): 40g mod 32 = 8g, conflict-free pattern
#define APAD 72   // V row stride
// dynamic smem (uint32): Khp[64][40] | Klp[64][40] | Vth[64][72]
#define AT_KHP 0
#define AT_KLP (64 * KP2)
#define AT_VTH (2 * 64 * KP2)
#define ATSMEM ((2 * 64 * KP2 + 64 * APAD) * 4)   // 38912 bytes

__global__ void __launch_bounds__(128) attn_tc_kernel(const float* __restrict__ gq,
                                                      const uint32_t* __restrict__ gkhp,
                                                      const uint32_t* __restrict__ gklp,
                                                      const float* __restrict__ gv,
                                                      const int* __restrict__ seq_id,
                                                      float* __restrict__ ctx) {
    extern __shared__ uint32_t smu[];
    uint32_t* Khp = smu + AT_KHP;   // [64][KP2]
    uint32_t* Klp = smu + AT_KLP;
    uint32_t* Vth = smu + AT_VTH;   // [DHD][APAD]
    __shared__ int sk_s[KT2];

    const int q0 = blockIdx.x * QT;
    const int h = blockIdx.y;
    const int b = blockIdx.z;
    const float* qbase = gq + (((size_t)b * HH + h) * LL) * DHD;
    const uint32_t* khb = gkhp + (((size_t)b * HH + h) * LL) * 32;
    const uint32_t* klb = gklp + (((size_t)b * HH + h) * LL) * 32;
    const float* vbase = gv + (((size_t)b * HH + h) * LL) * DHD;
    const int* sid = seq_id + (size_t)b * LL;

    const int tid = threadIdx.x;
    const int lane = tid & 31;
    const int wid = tid >> 5;
    const int g = lane >> 2, tg = lane & 3;
    const int wrow = wid * 16;

    // ---- Q fragments: bf16 hi/lo packed pairs, 4 chunks of k=16 ----
    // a0={g,2tg,2tg+1} a1={g+8,..} a2={g,8+2tg,9+2tg} a3={g+8,..}
    uint32_t qh[4][4], ql[4][4];
    {
        const float* r0 = qbase + (size_t)(q0 + wrow + g) * DHD;
        const float* r1 = qbase + (size_t)(q0 + wrow + g + 8) * DHD;
#pragma unroll
        for (int kc = 0; kc < 4; ++kc) {
            float2 p00 = *reinterpret_cast<const float2*>(r0 + 16 * kc + 2 * tg);
            float2 p10 = *reinterpret_cast<const float2*>(r1 + 16 * kc + 2 * tg);
            float2 p01 = *reinterpret_cast<const float2*>(r0 + 16 * kc + 8 + 2 * tg);
            float2 p11 = *reinterpret_cast<const float2*>(r1 + 16 * kc + 8 + 2 * tg);
            float f[8] = {p00.x * ATTN_SCALE, p00.y * ATTN_SCALE,
                          p10.x * ATTN_SCALE, p10.y * ATTN_SCALE,
                          p01.x * ATTN_SCALE, p01.y * ATTN_SCALE,
                          p11.x * ATTN_SCALE, p11.y * ATTN_SCALE};
            float hi[8], lo[8];
#pragma unroll
            for (int j = 0; j < 8; ++j) {
                hi[j] = bfh(f[j]);
                lo[j] = f[j] - hi[j];
            }
            qh[kc][0] = packbf(hi[0], hi[1]);
            qh[kc][1] = packbf(hi[2], hi[3]);
            qh[kc][2] = packbf(hi[4], hi[5]);
            qh[kc][3] = packbf(hi[6], hi[7]);
            ql[kc][0] = packbf(lo[0], lo[1]);
            ql[kc][1] = packbf(lo[2], lo[3]);
            ql[kc][2] = packbf(lo[4], lo[5]);
            ql[kc][3] = packbf(lo[6], lo[7]);
        }
    }

    const int sqr0 = sid[q0 + wrow + g];
    const int sqr1 = sid[q0 + wrow + g + 8];
    const int sqmin = sid[q0], sqmax = sid[q0 + QT - 1];

    float o[8][4] = {};
    float m0 = -1e30f, m1 = -1e30f, l0 = 0.f, l1 = 0.f;

    for (int k0 = 0; k0 < LL; k0 += KT2) {
        int kmin = sid[k0], kmax = sid[k0 + KT2 - 1];
        if (kmax < sqmin || kmin > sqmax) continue;

        __syncthreads();

        // ---- K tile: straight uint4 copy of packed bf16 hi/lo (perm pre-applied) ----
#pragma unroll
        for (int it = 0; it < 8; ++it) {
            int idx = tid + it * 128;        // 0..1023 uint4s
            int arr = idx >> 9;              // 0 = hi, 1 = lo
            int rest = idx & 511;
            int ki = rest >> 3;              // 0..63
            int c4 = rest & 7;               // 0..7 (uint4 within 32-u32 row)
            const uint32_t* src = (arr ? klb : khb) + (size_t)(k0 + ki) * 32 + c4 * 4;
            uint32_t* dstp = (arr ? Klp : Khp) + ki * KP2 + c4 * 4;
            *reinterpret_cast<uint4*>(dstp) = *reinterpret_cast<const uint4*>(src);
        }
        // ---- V tile 64x64: plain tf32, transposed, k-permuted ----
#pragma unroll
        for (int it = 0; it < 8; ++it) {
            int idx = tid + it * 128;
            int ki = idx & 63;
            int dc = ((idx >> 6) & 15) << 2;
            int pk = perm_k(ki);
            float4 v = *reinterpret_cast<const float4*>(vbase + (size_t)(k0 + ki) * DHD + dc);
            Vth[(dc + 0) * APAD + pk] = f2tf32(v.x);
            Vth[(dc + 1) * APAD + pk] = f2tf32(v.y);
            Vth[(dc + 2) * APAD + pk] = f2tf32(v.z);
            Vth[(dc + 3) * APAD + pk] = f2tf32(v.w);
        }
        if (tid < KT2) sk_s[tid] = sid[k0 + tid];
        __syncthreads();

        // ---- S = Q K^T : 3x bf16 m16n8k16 per (kc, nt) ----
        float s[8][4] = {};
#pragma unroll
        for (int kc = 0; kc < 4; ++kc) {
#pragma unroll
            for (int nt = 0; nt < 8; ++nt) {
                // b-frag pairs (tg, tg+4) are adjacent after perm
                uint2 bh2 = *reinterpret_cast<const uint2*>(&Khp[(nt * 8 + g) * KP2 + kc * 8 + 2 * tg]);
                uint2 bl2 = *reinterpret_cast<const uint2*>(&Klp[(nt * 8 + g) * KP2 + kc * 8 + 2 * tg]);
                uint32_t bh[2] = {bh2.x, bh2.y};
                uint32_t bl[2] = {bl2.x, bl2.y};
                mma_bf16(s[nt], qh[kc], bh);
                mma_bf16(s[nt], ql[kc], bh);
                mma_bf16(s[nt], qh[kc], bl);
            }
        }

        // ---- mask ----
#pragma unroll
        for (int nt = 0; nt < 8; ++nt) {
            int c = nt * 8 + 2 * tg;
            int sk0 = sk_s[c], sk1 = sk_s[c + 1];
            if (sqr0 != sk0) s[nt][0] = -1e30f;
            if (sqr0 != sk1) s[nt][1] = -1e30f;
            if (sqr1 != sk0) s[nt][2] = -1e30f;
            if (sqr1 != sk1) s[nt][3] = -1e30f;
        }

        // ---- online softmax over 64 keys ----
        float mx0 = -1e30f, mx1 = -1e30f;
#pragma unroll
        for (int nt = 0; nt < 8; ++nt) {
            mx0 = fmaxf(mx0, fmaxf(s[nt][0], s[nt][1]));
            mx1 = fmaxf(mx1, fmaxf(s[nt][2], s[nt][3]));
        }
        mx0 = fmaxf(mx0, __shfl_xor_sync(0xffffffffu, mx0, 1));
        mx0 = fmaxf(mx0, __shfl_xor_sync(0xffffffffu, mx0, 2));
        mx1 = fmaxf(mx1, __shfl_xor_sync(0xffffffffu, mx1, 1));
        mx1 = fmaxf(mx1, __shfl_xor_sync(0xffffffffu, mx1, 2));
        float mn0 = fmaxf(m0, mx0), mn1 = fmaxf(m1, mx1);
        float al0 = __expf(m0 - mn0), al1 = __expf(m1 - mn1);
        float ps0 = 0.f, ps1 = 0.f;
#pragma unroll
        for (int nt = 0; nt < 8; ++nt) {
            float p00 = (s[nt][0] < -1e29f) ? 0.f : __expf(s[nt][0] - mn0);
            float p01 = (s[nt][1] < -1e29f) ? 0.f : __expf(s[nt][1] - mn0);
            float p10 = (s[nt][2] < -1e29f) ? 0.f : __expf(s[nt][2] - mn1);
            float p11 = (s[nt][3] < -1e29f) ? 0.f : __expf(s[nt][3] - mn1);
            s[nt][0] = p00; s[nt][1] = p01; s[nt][2] = p10; s[nt][3] = p11;
            ps0 += p00 + p01;
            ps1 += p10 + p11;
        }
        ps0 += __shfl_xor_sync(0xffffffffu, ps0, 1);
        ps0 += __shfl_xor_sync(0xffffffffu, ps0, 2);
        ps1 += __shfl_xor_sync(0xffffffffu, ps1, 1);
        ps1 += __shfl_xor_sync(0xffffffffu, ps1, 2);
        l0 = l0 * al0 + ps0;
        l1 = l1 * al1 + ps1;
        m0 = mn0; m1 = mn1;

#pragma unroll
        for (int dt = 0; dt < 8; ++dt) {
            o[dt][0] *= al0; o[dt][1] *= al0;
            o[dt][2] *= al1; o[dt][3] *= al1;
        }

        // ---- O += P V (plain TF32, unchanged) ----
#pragma unroll
        for (int nt = 0; nt < 8; ++nt) {
            int s0l = (lane & ~3) | (tg >> 1);
            int s1l = s0l + 2;
            float e0 = __shfl_sync(0xffffffffu, s[nt][0], s0l);
            float e1 = __shfl_sync(0xffffffffu, s[nt][1], s0l);
            float e2 = __shfl_sync(0xffffffffu, s[nt][2], s0l);
            float e3 = __shfl_sync(0xffffffffu, s[nt][3], s0l);
            float f0 = __shfl_sync(0xffffffffu, s[nt][0], s1l);
            float f1 = __shfl_sync(0xffffffffu, s[nt][1], s1l);
            float f2 = __shfl_sync(0xffffffffu, s[nt][2], s1l);
            float f3 = __shfl_sync(0xffffffffu, s[nt][3], s1l);
            bool odd = (tg & 1);
            float a0f = odd ? e1 : e0;
            float a1f = odd ? e3 : e2;
            float a2f = odd ? f1 : f0;
            float a3f = odd ? f3 : f2;
            uint32_t ah[4];
            ah[0] = f2tf32(a0f);
            ah[1] = f2tf32(a1f);
            ah[2] = f2tf32(a2f);
            ah[3] = f2tf32(a3f);
#pragma unroll
            for (int dt = 0; dt < 8; ++dt) {
                uint2 vh2 = *reinterpret_cast<const uint2*>(&Vth[(dt * 8 + g) * APAD + 8 * nt + 2 * tg]);
                uint32_t bh[2] = {vh2.x, vh2.y};
                mma_tf32(o[dt], ah, bh);
            }
        }
    }

    // epilogue: pre-round ctx to tf32 grid (feeds the raw-bit out-proj GEMM)
    float invl0 = 1.f / l0, invl1 = 1.f / l1;
    size_t row0 = ((size_t)b * LL + q0 + wrow + g) * DD + h * DHD;
    size_t row1 = ((size_t)b * LL + q0 + wrow + g + 8) * DD + h * DHD;
#pragma unroll
    for (int dt = 0; dt < 8; ++dt) {
        int col = dt * 8 + 2 * tg;
        *reinterpret_cast<float2*>(ctx + row0 + col) =
            make_float2(rnd_tf32(o[dt][0] * invl0), rnd_tf32(o[dt][1] * invl0));
        *reinterpret_cast<float2*>(ctx + row1 + col) =
            make_float2(rnd_tf32(o[dt][2] * invl1), rnd_tf32(o[dt][3] * invl1));
    }
}

// -------------------- launch --------------------
extern "C" void kernel_launch(void* const* d_in, const int* in_sizes, int n_in,
                              void* d_out, int out_size) {
    const float* x      = (const float*)d_in[0];
    const int*   seq    = (const int*)  d_in[1];
    const float* ln_w   = (const float*)d_in[2];
    const float* ln_b   = (const float*)d_in[3];
    const float* w_qkv  = (const float*)d_in[4];
    const float* qa     = (const float*)d_in[5];
    const float* qb     = (const float*)d_in[6];
    const float* va     = (const float*)d_in[7];
    const float* vb     = (const float*)d_in[8];
    const float* q_ln_w = (const float*)d_in[9];
    const float* k_ln_w = (const float*)d_in[10];
    const float* w_out  = (const float*)d_in[11];
    float* out = (float*)d_out;

    float *ph, *pweff, *pqkv, *pq, *pv, *pctx, *prc, *prs, *pwo;
    uint32_t *pkhp, *pklp;
    cudaGetSymbolAddress((void**)&ph,    g_h);
    cudaGetSymbolAddress((void**)&pweff, g_weff);
    cudaGetSymbolAddress((void**)&pqkv,  g_qkv);
    cudaGetSymbolAddress((void**)&pq,    g_q);
    cudaGetSymbolAddress((void**)&pkhp,  g_khp);
    cudaGetSymbolAddress((void**)&pklp,  g_klp);
    cudaGetSymbolAddress((void**)&pv,    g_v);
    cudaGetSymbolAddress((void**)&pctx,  g_ctx);
    cudaGetSymbolAddress((void**)&prc,   g_rcos);
    cudaGetSymbolAddress((void**)&prs,   g_rsin);
    cudaGetSymbolAddress((void**)&pwo,   g_wout_r);

    cudaFuncSetAttribute(gemm_tf32, cudaFuncAttributeMaxDynamicSharedMemorySize, SMEM_GEMM);
    cudaFuncSetAttribute(attn_tc_kernel, cudaFuncAttributeMaxDynamicSharedMemorySize, ATSMEM);

    rope_table_kernel<<<(LL * 32 + 255) / 256, 256>>>(prc, prs);
    ln_kernel<<<NROWS, 256>>>(x, ln_w, ln_b, ph);
    weff_kernel<<<(4 * DD * DD + 255) / 256, 256>>>(w_qkv, qa, qb, va, vb, w_out, pwo, pweff);
    gemm_tf32<<<dim3(3 * DD / BN, NROWS / BM), 128, SMEM_GEMM>>>(ph, pweff, pqkv, NROWS, 3 * DD, DD);
    transform_kernel<<<NROWS, 256>>>(pqkv, q_ln_w, k_ln_w, prc, prs, pq, pkhp, pklp, pv);
    attn_tc_kernel<<<dim3(LL / QT, HH, BB), 128, ATSMEM>>>(pq, pkhp, pklp, pv, seq, pctx);
    gemm_tf32<<<dim3(DD / BN, NROWS / BM), 128, SMEM_GEMM>>>(pctx, pwo, out, NROWS, DD, DD);
}

// round 17
// speedup vs baseline: 1.5171x; 1.0643x over previous
#include <cuda_runtime.h>
#include <cuda_bf16.h>
#include <math.h>
#include <stddef.h>
#include <stdint.h>

// Problem constants
#define BB 2
#define LL 2048
#define DD 1024
#define HH 16
#define DHD 64
#define RR 32
#define NROWS (BB*LL)          // 4096
#define LORA_SCALE 2.0f
#define ATTN_SCALE 0.125f      // 1/sqrt(64)

// -------------------- scratch (static device memory, allowed) --------------------
__device__ float g_h[NROWS * DD];          // tf32-rounded LN(x)
__device__ float g_weff[3 * DD * DD];      // tf32-rounded qkv weight + lora
__device__ float g_qkv[NROWS * 3 * DD];
__device__ float g_q[BB * HH * LL * DHD];  // [B,H,L,DH]
__device__ uint32_t g_khp[BB * HH * LL * 32];  // [B,H,L,perm(pair)] bf16x2 hi of rope'd k
__device__ uint32_t g_klp[BB * HH * LL * 32];  // bf16x2 lo
__device__ float g_v[BB * HH * LL * DHD];
__device__ float g_ctx[NROWS * DD];        // tf32-rounded attention output
__device__ float g_rcos[LL * 32];
__device__ float g_rsin[LL * 32];
__device__ float g_wout_r[DD * DD];        // tf32-rounded w_out

// -------------------- helpers --------------------
__device__ __forceinline__ uint32_t f2tf32(float f) {
    uint32_t r;
    asm("cvt.rna.tf32.f32 %0, %1;" : "=r"(r) : "f"(f));
    return r;
}
__device__ __forceinline__ float rnd_tf32(float f) {
    return __uint_as_float(f2tf32(f));
}
__device__ __forceinline__ uint32_t packbf(float lo, float hi) {
    __nv_bfloat162 p = __floats2bfloat162_rn(lo, hi);
    return *reinterpret_cast<uint32_t*>(&p);
}
__device__ __forceinline__ float bfh(float x) {
    return __bfloat162float(__float2bfloat16_rn(x));
}

__device__ __forceinline__ void mma_tf32(float* c, const uint32_t* a, const uint32_t* b) {
    asm volatile(
        "mma.sync.aligned.m16n8k8.row.col.f32.tf32.tf32.f32 "
        "{%0,%1,%2,%3}, {%4,%5,%6,%7}, {%8,%9}, {%0,%1,%2,%3};\n"
        : "+f"(c[0]), "+f"(c[1]), "+f"(c[2]), "+f"(c[3])
        : "r"(a[0]), "r"(a[1]), "r"(a[2]), "r"(a[3]), "r"(b[0]), "r"(b[1]));
}

__device__ __forceinline__ void mma_bf16(float* c, const uint32_t* a, const uint32_t* b) {
    asm volatile(
        "mma.sync.aligned.m16n8k16.row.col.f32.bf16.bf16.f32 "
        "{%0,%1,%2,%3}, {%4,%5,%6,%7}, {%8,%9}, {%0,%1,%2,%3};\n"
        : "+f"(c[0]), "+f"(c[1]), "+f"(c[2]), "+f"(c[3])
        : "r"(a[0]), "r"(a[1]), "r"(a[2]), "r"(a[3]), "r"(b[0]), "r"(b[1]));
}

__device__ __forceinline__ void cp_async16(uint32_t saddr, const void* gptr) {
    asm volatile("cp.async.ca.shared.global [%0], [%1], 16;\n" :: "r"(saddr), "l"(gptr));
}
__device__ __forceinline__ void cp_commit() {
    asm volatile("cp.async.commit_group;\n");
}
template<int N>
__device__ __forceinline__ void cp_wait() {
    asm volatile("cp.async.wait_group %0;\n" :: "n"(N));
}

__device__ __forceinline__ float4 block_reduce4(float4 v, float4* buf) {
#pragma unroll
    for (int o = 16; o; o >>= 1) {
        v.x += __shfl_xor_sync(0xffffffffu, v.x, o);
        v.y += __shfl_xor_sync(0xffffffffu, v.y, o);
        v.z += __shfl_xor_sync(0xffffffffu, v.z, o);
        v.w += __shfl_xor_sync(0xffffffffu, v.w, o);
    }
    int w = threadIdx.x >> 5, lane = threadIdx.x & 31;
    if (lane == 0) buf[w] = v;
    __syncthreads();
    if (w == 0) {
        v = (lane < 8) ? buf[lane] : make_float4(0.f, 0.f, 0.f, 0.f);
#pragma unroll
        for (int o = 4; o; o >>= 1) {
            v.x += __shfl_xor_sync(0xffffffffu, v.x, o);
            v.y += __shfl_xor_sync(0xffffffffu, v.y, o);
            v.z += __shfl_xor_sync(0xffffffffu, v.z, o);
            v.w += __shfl_xor_sync(0xffffffffu, v.w, o);
        }
        if (lane == 0) buf[0] = v;
    }
    __syncthreads();
    return buf[0];
}

// -------------------- 0) RoPE table --------------------
__global__ void rope_table_kernel(float* __restrict__ rc, float* __restrict__ rs) {
    int i = blockIdx.x * blockDim.x + threadIdx.x;
    if (i >= LL * 32) return;
    int l = i >> 5, jj = i & 31;
    double invf = exp(-0.28782313662425575 * (double)jj);
    double ang = (double)l * invf;
    double sd, cd;
    sincos(ang, &sd, &cd);
    rc[i] = (float)cd;
    rs[i] = (float)sd;
}

// -------------------- 1) input LayerNorm (pre-rounded output) --------------------
__global__ void ln_kernel(const float* __restrict__ x, const float* __restrict__ w,
                          const float* __restrict__ b, float* __restrict__ out) {
    __shared__ float4 buf[8];
    int n = blockIdx.x;
    int tid = threadIdx.x;
    const float4* xr = reinterpret_cast<const float4*>(x + (size_t)n * DD);
    float4 xv = xr[tid];
    float4 sums = make_float4(xv.x + xv.y + xv.z + xv.w,
                              xv.x * xv.x + xv.y * xv.y + xv.z * xv.z + xv.w * xv.w,
                              0.f, 0.f);
    float4 r = block_reduce4(sums, buf);
    float mu = r.x * (1.f / DD);
    float var = r.y * (1.f / DD) - mu * mu;
    float inv = rsqrtf(var + 1e-5f);
    float4 wv = reinterpret_cast<const float4*>(w)[tid];
    float4 bv = reinterpret_cast<const float4*>(b)[tid];
    float4 o;
    o.x = rnd_tf32((xv.x - mu) * inv * wv.x + bv.x);
    o.y = rnd_tf32((xv.y - mu) * inv * wv.y + bv.y);
    o.z = rnd_tf32((xv.z - mu) * inv * wv.z + bv.z);
    o.w = rnd_tf32((xv.w - mu) * inv * wv.w + bv.w);
    reinterpret_cast<float4*>(out + (size_t)n * DD)[tid] = o;
}

// -------------------- 2) fold LoRA into QKV weight + round w_out (fused) ----------
__global__ void weff_kernel(const float* __restrict__ wqkv,
                            const float* __restrict__ qa, const float* __restrict__ qb,
                            const float* __restrict__ va, const float* __restrict__ vb,
                            const float* __restrict__ wout, float* __restrict__ woutr,
                            float* __restrict__ weff) {
    int idx = blockIdx.x * blockDim.x + threadIdx.x;
    if (idx >= 4 * DD * DD) return;
    if (idx >= 3 * DD * DD) {
        int i = idx - 3 * DD * DD;
        woutr[i] = rnd_tf32(wout[i]);
        return;
    }
    int e = idx >> 10, d = idx & 1023;
    float w = wqkv[idx];
    if (e < DD) {
        float s = 0.f;
#pragma unroll
        for (int r = 0; r < RR; ++r) s += qb[e * RR + r] * qa[r * DD + d];
        w += LORA_SCALE * s;
    } else if (e >= 2 * DD) {
        int eb = e - 2 * DD;
        float s = 0.f;
#pragma unroll
        for (int r = 0; r < RR; ++r) s += vb[eb * RR + r] * va[r * DD + d];
        w += LORA_SCALE * s;
    }
    weff[idx] = rnd_tf32(w);
}

// -------------------- 3/6) TF32 GEMM: BK=32, 2-stage cp.async, 64x64 warp tile ------
#define BM 128
#define BN 128
#define BK 32
#define SKW (BK + 8)   // 40: LDS.64 banks 8g+2tg distinct per half-warp phase
#define GSTG 2
#define SMEM_GEMM (GSTG * 2 * BM * SKW * 4)   // 81920 bytes

#define AS(s, r, c) sm_a[((s) * BM + (r)) * SKW + (c)]
#define WS(s, r, c) sm_w[((s) * BN + (r)) * SKW + (c)]

__global__ void __launch_bounds__(128, 2) gemm_tf32(const float* __restrict__ A,
                                                    const float* __restrict__ W,
                                                    float* __restrict__ C,
                                                    int M, int N, int K) {
    extern __shared__ uint32_t sm[];
    uint32_t* sm_a = sm;
    uint32_t* sm_w = sm + GSTG * BM * SKW;

    const int tid = threadIdx.x;
    const int lane = tid & 31;
    const int wid = tid >> 5;               // 0..3
    const int g = lane >> 2, tg = lane & 3;
    const int wm = wid >> 1, wn = wid & 1;  // 2 x 2 warp grid, 64x64 warp tile
    const int bm = blockIdx.y * BM, bn = blockIdx.x * BN;

    // per-thread global load slots: 8 float4 per operand per tile (128 rows x 32 cols)
    int row_[8], kc_[8];
#pragma unroll
    for (int l = 0; l < 8; ++l) {
        int idx = tid + l * 128;            // 0..1023
        row_[l] = idx >> 3;                 // 0..127
        kc_[l] = (idx & 7) << 2;            // 0,4,...,28
    }

    const float* gA = A + (size_t)bm * K;
    const float* gW = W + (size_t)bn * K;

    auto issue = [&](int s, int t) {
#pragma unroll
        for (int l = 0; l < 8; ++l) {
            uint32_t sa = (uint32_t)__cvta_generic_to_shared(&AS(s, row_[l], kc_[l]));
            cp_async16(sa, gA + (size_t)row_[l] * K + t * BK + kc_[l]);
            uint32_t sw = (uint32_t)__cvta_generic_to_shared(&WS(s, row_[l], kc_[l]));
            cp_async16(sw, gW + (size_t)row_[l] * K + t * BK + kc_[l]);
        }
        cp_commit();
    };

    const int nk = K / BK;                  // 32
    issue(0, 0);

    float c[4][8][4] = {};

    for (int t = 0; t < nk; ++t) {
        cp_wait<0>();                       // only tile t's group is outstanding
        __syncthreads();                    // also: compute(t-1) done -> buffer (t+1)%2 free
        if (t + 1 < nk) issue((t + 1) & 1, t + 1);

        const int buf = t & 1;
#pragma unroll
        for (int ks = 0; ks < BK; ks += 8) {
            uint32_t af[4][4], bf[8][2];
#pragma unroll
            for (int mt = 0; mt < 4; ++mt) {
                int m = wm * 64 + mt * 16;
                uint2 a0 = *reinterpret_cast<const uint2*>(&AS(buf, m + g,     ks + 2 * tg));
                uint2 a1 = *reinterpret_cast<const uint2*>(&AS(buf, m + g + 8, ks + 2 * tg));
                af[mt][0] = a0.x; af[mt][2] = a0.y;
                af[mt][1] = a1.x; af[mt][3] = a1.y;
            }
#pragma unroll
            for (int nt = 0; nt < 8; ++nt) {
                int n = wn * 64 + nt * 8;
                uint2 b0 = *reinterpret_cast<const uint2*>(&WS(buf, n + g, ks + 2 * tg));
                bf[nt][0] = b0.x; bf[nt][1] = b0.y;
            }
#pragma unroll
            for (int mt = 0; mt < 4; ++mt)
#pragma unroll
                for (int nt = 0; nt < 8; ++nt)
                    mma_tf32(c[mt][nt], af[mt], bf[nt]);
        }
    }

#pragma unroll
    for (int mt = 0; mt < 4; ++mt) {
        int row0 = bm + wm * 64 + mt * 16 + g;
#pragma unroll
        for (int nt = 0; nt < 8; ++nt) {
            int col = bn + wn * 64 + nt * 8 + 2 * tg;
            *reinterpret_cast<float2*>(C + (size_t)row0 * N + col) =
                make_float2(c[mt][nt][0], c[mt][nt][1]);
            *reinterpret_cast<float2*>(C + (size_t)(row0 + 8) * N + col) =
                make_float2(c[mt][nt][2], c[mt][nt][3]);
        }
    }
}

// -------------------- pair-index perm (8-blockwise) --------------------
__device__ __forceinline__ int perm_k(int d) {
    return (d & ~7) + 2 * (d & 3) + ((d >> 2) & 1);
}

// -------------------- 4) q/k LN + RoPE; k -> packed bf16 hi/lo, perm'd -------------
__global__ void transform_kernel(const float* __restrict__ qkv,
                                 const float* __restrict__ qw, const float* __restrict__ kw,
                                 const float* __restrict__ rcos, const float* __restrict__ rsin,
                                 float* __restrict__ gq,
                                 uint32_t* __restrict__ gkhp, uint32_t* __restrict__ gklp,
                                 float* __restrict__ gv) {
    __shared__ float sq[DD];
    __shared__ float sk[DD];
    __shared__ float4 buf[8];
    int n = blockIdx.x;
    int b = n >> 11, l = n & 2047;
    int tid = threadIdx.x;
    const float* row = qkv + (size_t)n * (3 * DD);
    float4 qv = reinterpret_cast<const float4*>(row)[tid];
    float4 kv = reinterpret_cast<const float4*>(row + DD)[tid];
    float4 vv = reinterpret_cast<const float4*>(row + 2 * DD)[tid];

    {
        int d = tid * 4;
        int h = d >> 6, j = d & 63;
        float* dst = gv + ((((size_t)b * HH + h) * LL + l) * DHD + j);
        *reinterpret_cast<float4*>(dst) = vv;
    }

    float4 sums = make_float4(qv.x + qv.y + qv.z + qv.w,
                              qv.x * qv.x + qv.y * qv.y + qv.z * qv.z + qv.w * qv.w,
                              kv.x + kv.y + kv.z + kv.w,
                              kv.x * kv.x + kv.y * kv.y + kv.z * kv.z + kv.w * kv.w);
    float4 r = block_reduce4(sums, buf);
    float muq = r.x * (1.f / DD), ivq = rsqrtf(r.y * (1.f / DD) - muq * muq + 1e-5f);
    float muk = r.z * (1.f / DD), ivk = rsqrtf(r.w * (1.f / DD) - muk * muk + 1e-5f);
    float4 qwv = reinterpret_cast<const float4*>(qw)[tid];
    float4 kwv = reinterpret_cast<const float4*>(kw)[tid];
    int d0 = tid * 4;
    sq[d0 + 0] = (qv.x - muq) * ivq * qwv.x;
    sq[d0 + 1] = (qv.y - muq) * ivq * qwv.y;
    sq[d0 + 2] = (qv.z - muq) * ivq * qwv.z;
    sq[d0 + 3] = (qv.w - muq) * ivq * qwv.w;
    sk[d0 + 0] = (kv.x - muk) * ivk * kwv.x;
    sk[d0 + 1] = (kv.y - muk) * ivk * kwv.y;
    sk[d0 + 2] = (kv.z - muk) * ivk * kwv.z;
    sk[d0 + 3] = (kv.w - muk) * ivk * kwv.w;
    __syncthreads();

    float oq[4], ok[4];
#pragma unroll
    for (int c = 0; c < 4; ++c) {
        int d = d0 + c;
        int j = d & 63;
        int jj = j & 31;
        float cs = rcos[l * 32 + jj];
        float sn = rsin[l * 32 + jj];
        if (j < 32) {
            oq[c] = sq[d] * cs - sq[d + 32] * sn;
            ok[c] = sk[d] * cs - sk[d + 32] * sn;
        } else {
            oq[c] = sq[d] * cs + sq[d - 32] * sn;
            ok[c] = sk[d] * cs + sk[d - 32] * sn;
        }
    }
    int h = d0 >> 6, j0 = d0 & 63;
    size_t qb_ = (((size_t)b * HH + h) * LL + l) * DHD + j0;
    *reinterpret_cast<float4*>(gq + qb_) = make_float4(oq[0], oq[1], oq[2], oq[3]);

    size_t kb_ = (((size_t)b * HH + h) * LL + l) * 32;
    int jp = (j0 >> 1);
    float h0 = bfh(ok[0]), h1 = bfh(ok[1]), h2 = bfh(ok[2]), h3 = bfh(ok[3]);
    gkhp[kb_ + perm_k(jp)]     = packbf(h0, h1);
    gkhp[kb_ + perm_k(jp + 1)] = packbf(h2, h3);
    float l0v = bfh(ok[0] - h0), l1v = bfh(ok[1] - h1);
    float l2v = bfh(ok[2] - h2), l3v = bfh(ok[3] - h3);
    gklp[kb_ + perm_k(jp)]     = packbf(l0v, l1v);
    gklp[kb_ + perm_k(jp + 1)] = packbf(l2v, l3v);
}

// -------------------- 5) flash attention: S = 3x bf16 m16n8k16, PV = tf32 (R16) ----
#define QT 64
#define KT2 64
#define KP2 40
#define APAD 72
#define AT_KHP 0
#define AT_KLP (64 * KP2)
#define AT_VTH (2 * 64 * KP2)
#define ATSMEM ((2 * 64 * KP2 + 64 * APAD) * 4)   // 38912 bytes

__global__ void __launch_bounds__(128) attn_tc_kernel(const float* __restrict__ gq,
                                                      const uint32_t* __restrict__ gkhp,
                                                      const uint32_t* __restrict__ gklp,
                                                      const float* __restrict__ gv,
                                                      const int* __restrict__ seq_id,
                                                      float* __restrict__ ctx) {
    extern __shared__ uint32_t smu[];
    uint32_t* Khp = smu + AT_KHP;
    uint32_t* Klp = smu + AT_KLP;
    uint32_t* Vth = smu + AT_VTH;
    __shared__ int sk_s[KT2];

    const int q0 = blockIdx.x * QT;
    const int h = blockIdx.y;
    const int b = blockIdx.z;
    const float* qbase = gq + (((size_t)b * HH + h) * LL) * DHD;
    const uint32_t* khb = gkhp + (((size_t)b * HH + h) * LL) * 32;
    const uint32_t* klb = gklp + (((size_t)b * HH + h) * LL) * 32;
    const float* vbase = gv + (((size_t)b * HH + h) * LL) * DHD;
    const int* sid = seq_id + (size_t)b * LL;

    const int tid = threadIdx.x;
    const int lane = tid & 31;
    const int wid = tid >> 5;
    const int g = lane >> 2, tg = lane & 3;
    const int wrow = wid * 16;

    uint32_t qh[4][4], ql[4][4];
    {
        const float* r0 = qbase + (size_t)(q0 + wrow + g) * DHD;
        const float* r1 = qbase + (size_t)(q0 + wrow + g + 8) * DHD;
#pragma unroll
        for (int kc = 0; kc < 4; ++kc) {
            float2 p00 = *reinterpret_cast<const float2*>(r0 + 16 * kc + 2 * tg);
            float2 p10 = *reinterpret_cast<const float2*>(r1 + 16 * kc + 2 * tg);
            float2 p01 = *reinterpret_cast<const float2*>(r0 + 16 * kc + 8 + 2 * tg);
            float2 p11 = *reinterpret_cast<const float2*>(r1 + 16 * kc + 8 + 2 * tg);
            float f[8] = {p00.x * ATTN_SCALE, p00.y * ATTN_SCALE,
                          p10.x * ATTN_SCALE, p10.y * ATTN_SCALE,
                          p01.x * ATTN_SCALE, p01.y * ATTN_SCALE,
                          p11.x * ATTN_SCALE, p11.y * ATTN_SCALE};
            float hi[8], lo[8];
#pragma unroll
            for (int j = 0; j < 8; ++j) {
                hi[j] = bfh(f[j]);
                lo[j] = f[j] - hi[j];
            }
            qh[kc][0] = packbf(hi[0], hi[1]);
            qh[kc][1] = packbf(hi[2], hi[3]);
            qh[kc][2] = packbf(hi[4], hi[5]);
            qh[kc][3] = packbf(hi[6], hi[7]);
            ql[kc][0] = packbf(lo[0], lo[1]);
            ql[kc][1] = packbf(lo[2], lo[3]);
            ql[kc][2] = packbf(lo[4], lo[5]);
            ql[kc][3] = packbf(lo[6], lo[7]);
        }
    }

    const int sqr0 = sid[q0 + wrow + g];
    const int sqr1 = sid[q0 + wrow + g + 8];
    const int sqmin = sid[q0], sqmax = sid[q0 + QT - 1];

    float o[8][4] = {};
    float m0 = -1e30f, m1 = -1e30f, l0 = 0.f, l1 = 0.f;

    for (int k0 = 0; k0 < LL; k0 += KT2) {
        int kmin = sid[k0], kmax = sid[k0 + KT2 - 1];
        if (kmax < sqmin || kmin > sqmax) continue;

        __syncthreads();

#pragma unroll
        for (int it = 0; it < 8; ++it) {
            int idx = tid + it * 128;
            int arr = idx >> 9;
            int rest = idx & 511;
            int ki = rest >> 3;
            int c4 = rest & 7;
            const uint32_t* src = (arr ? klb : khb) + (size_t)(k0 + ki) * 32 + c4 * 4;
            uint32_t* dstp = (arr ? Klp : Khp) + ki * KP2 + c4 * 4;
            *reinterpret_cast<uint4*>(dstp) = *reinterpret_cast<const uint4*>(src);
        }
#pragma unroll
        for (int it = 0; it < 8; ++it) {
            int idx = tid + it * 128;
            int ki = idx & 63;
            int dc = ((idx >> 6) & 15) << 2;
            int pk = perm_k(ki);
            float4 v = *reinterpret_cast<const float4*>(vbase + (size_t)(k0 + ki) * DHD + dc);
            Vth[(dc + 0) * APAD + pk] = f2tf32(v.x);
            Vth[(dc + 1) * APAD + pk] = f2tf32(v.y);
            Vth[(dc + 2) * APAD + pk] = f2tf32(v.z);
            Vth[(dc + 3) * APAD + pk] = f2tf32(v.w);
        }
        if (tid < KT2) sk_s[tid] = sid[k0 + tid];
        __syncthreads();

        float s[8][4] = {};
#pragma unroll
        for (int kc = 0; kc < 4; ++kc) {
#pragma unroll
            for (int nt = 0; nt < 8; ++nt) {
                uint2 bh2 = *reinterpret_cast<const uint2*>(&Khp[(nt * 8 + g) * KP2 + kc * 8 + 2 * tg]);
                uint2 bl2 = *reinterpret_cast<const uint2*>(&Klp[(nt * 8 + g) * KP2 + kc * 8 + 2 * tg]);
                uint32_t bh[2] = {bh2.x, bh2.y};
                uint32_t bl[2] = {bl2.x, bl2.y};
                mma_bf16(s[nt], qh[kc], bh);
                mma_bf16(s[nt], ql[kc], bh);
                mma_bf16(s[nt], qh[kc], bl);
            }
        }

#pragma unroll
        for (int nt = 0; nt < 8; ++nt) {
            int c = nt * 8 + 2 * tg;
            int sk0 = sk_s[c], sk1 = sk_s[c + 1];
            if (sqr0 != sk0) s[nt][0] = -1e30f;
            if (sqr0 != sk1) s[nt][1] = -1e30f;
            if (sqr1 != sk0) s[nt][2] = -1e30f;
            if (sqr1 != sk1) s[nt][3] = -1e30f;
        }

        float mx0 = -1e30f, mx1 = -1e30f;
#pragma unroll
        for (int nt = 0; nt < 8; ++nt) {
            mx0 = fmaxf(mx0, fmaxf(s[nt][0], s[nt][1]));
            mx1 = fmaxf(mx1, fmaxf(s[nt][2], s[nt][3]));
        }
        mx0 = fmaxf(mx0, __shfl_xor_sync(0xffffffffu, mx0, 1));
        mx0 = fmaxf(mx0, __shfl_xor_sync(0xffffffffu, mx0, 2));
        mx1 = fmaxf(mx1, __shfl_xor_sync(0xffffffffu, mx1, 1));
        mx1 = fmaxf(mx1, __shfl_xor_sync(0xffffffffu, mx1, 2));
        float mn0 = fmaxf(m0, mx0), mn1 = fmaxf(m1, mx1);
        float al0 = __expf(m0 - mn0), al1 = __expf(m1 - mn1);
        float ps0 = 0.f, ps1 = 0.f;
#pragma unroll
        for (int nt = 0; nt < 8; ++nt) {
            float p00 = (s[nt][0] < -1e29f) ? 0.f : __expf(s[nt][0] - mn0);
            float p01 = (s[nt][1] < -1e29f) ? 0.f : __expf(s[nt][1] - mn0);
            float p10 = (s[nt][2] < -1e29f) ? 0.f : __expf(s[nt][2] - mn1);
            float p11 = (s[nt][3] < -1e29f) ? 0.f : __expf(s[nt][3] - mn1);
            s[nt][0] = p00; s[nt][1] = p01; s[nt][2] = p10; s[nt][3] = p11;
            ps0 += p00 + p01;
            ps1 += p10 + p11;
        }
        ps0 += __shfl_xor_sync(0xffffffffu, ps0, 1);
        ps0 += __shfl_xor_sync(0xffffffffu, ps0, 2);
        ps1 += __shfl_xor_sync(0xffffffffu, ps1, 1);
        ps1 += __shfl_xor_sync(0xffffffffu, ps1, 2);
        l0 = l0 * al0 + ps0;
        l1 = l1 * al1 + ps1;
        m0 = mn0; m1 = mn1;

#pragma unroll
        for (int dt = 0; dt < 8; ++dt) {
            o[dt][0] *= al0; o[dt][1] *= al0;
            o[dt][2] *= al1; o[dt][3] *= al1;
        }

#pragma unroll
        for (int nt = 0; nt < 8; ++nt) {
            int s0l = (lane & ~3) | (tg >> 1);
            int s1l = s0l + 2;
            float e0 = __shfl_sync(0xffffffffu, s[nt][0], s0l);
            float e1 = __shfl_sync(0xffffffffu, s[nt][1], s0l);
            float e2 = __shfl_sync(0xffffffffu, s[nt][2], s0l);
            float e3 = __shfl_sync(0xffffffffu, s[nt][3], s0l);
            float f0 = __shfl_sync(0xffffffffu, s[nt][0], s1l);
            float f1 = __shfl_sync(0xffffffffu, s[nt][1], s1l);
            float f2 = __shfl_sync(0xffffffffu, s[nt][2], s1l);
            float f3 = __shfl_sync(0xffffffffu, s[nt][3], s1l);
            bool odd = (tg & 1);
            float a0f = odd ? e1 : e0;
            float a1f = odd ? e3 : e2;
            float a2f = odd ? f1 : f0;
            float a3f = odd ? f3 : f2;
            uint32_t ah[4];
            ah[0] = f2tf32(a0f);
            ah[1] = f2tf32(a1f);
            ah[2] = f2tf32(a2f);
            ah[3] = f2tf32(a3f);
#pragma unroll
            for (int dt = 0; dt < 8; ++dt) {
                uint2 vh2 = *reinterpret_cast<const uint2*>(&Vth[(dt * 8 + g) * APAD + 8 * nt + 2 * tg]);
                uint32_t bh[2] = {vh2.x, vh2.y};
                mma_tf32(o[dt], ah, bh);
            }
        }
    }

    float invl0 = 1.f / l0, invl1 = 1.f / l1;
    size_t row0 = ((size_t)b * LL + q0 + wrow + g) * DD + h * DHD;
    size_t row1 = ((size_t)b * LL + q0 + wrow + g + 8) * DD + h * DHD;
#pragma unroll
    for (int dt = 0; dt < 8; ++dt) {
        int col = dt * 8 + 2 * tg;
        *reinterpret_cast<float2*>(ctx + row0 + col) =
            make_float2(rnd_tf32(o[dt][0] * invl0), rnd_tf32(o[dt][1] * invl0));
        *reinterpret_cast<float2*>(ctx + row1 + col) =
            make_float2(rnd_tf32(o[dt][2] * invl1), rnd_tf32(o[dt][3] * invl1));
    }
}

// -------------------- launch --------------------
extern "C" void kernel_launch(void* const* d_in, const int* in_sizes, int n_in,
                              void* d_out, int out_size) {
    const float* x      = (const float*)d_in[0];
    const int*   seq    = (const int*)  d_in[1];
    const float* ln_w   = (const float*)d_in[2];
    const float* ln_b   = (const float*)d_in[3];
    const float* w_qkv  = (const float*)d_in[4];
    const float* qa     = (const float*)d_in[5];
    const float* qb     = (const float*)d_in[6];
    const float* va     = (const float*)d_in[7];
    const float* vb     = (const float*)d_in[8];
    const float* q_ln_w = (const float*)d_in[9];
    const float* k_ln_w = (const float*)d_in[10];
    const float* w_out  = (const float*)d_in[11];
    float* out = (float*)d_out;

    float *ph, *pweff, *pqkv, *pq, *pv, *pctx, *prc, *prs, *pwo;
    uint32_t *pkhp, *pklp;
    cudaGetSymbolAddress((void**)&ph,    g_h);
    cudaGetSymbolAddress((void**)&pweff, g_weff);
    cudaGetSymbolAddress((void**)&pqkv,  g_qkv);
    cudaGetSymbolAddress((void**)&pq,    g_q);
    cudaGetSymbolAddress((void**)&pkhp,  g_khp);
    cudaGetSymbolAddress((void**)&pklp,  g_klp);
    cudaGetSymbolAddress((void**)&pv,    g_v);
    cudaGetSymbolAddress((void**)&pctx,  g_ctx);
    cudaGetSymbolAddress((void**)&prc,   g_rcos);
    cudaGetSymbolAddress((void**)&prs,   g_rsin);
    cudaGetSymbolAddress((void**)&pwo,   g_wout_r);

    cudaFuncSetAttribute(gemm_tf32, cudaFuncAttributeMaxDynamicSharedMemorySize, SMEM_GEMM);
    cudaFuncSetAttribute(attn_tc_kernel, cudaFuncAttributeMaxDynamicSharedMemorySize, ATSMEM);

    rope_table_kernel<<<(LL * 32 + 255) / 256, 256>>>(prc, prs);
    ln_kernel<<<NROWS, 256>>>(x, ln_w, ln_b, ph);
    weff_kernel<<<(4 * DD * DD + 255) / 256, 256>>>(w_qkv, qa, qb, va, vb, w_out, pwo, pweff);
    gemm_tf32<<<dim3(3 * DD / BN, NROWS / BM), 128, SMEM_GEMM>>>(ph, pweff, pqkv, NROWS, 3 * DD, DD);
    transform_kernel<<<NROWS, 256>>>(pqkv, q_ln_w, k_ln_w, prc, prs, pq, pkhp, pklp, pv);
    attn_tc_kernel<<<dim3(LL / QT, HH, BB), 128, ATSMEM>>>(pq, pkhp, pklp, pv, seq, pctx);
    gemm_tf32<<<dim3(DD / BN, NROWS / BM), 128, SMEM_GEMM>>>(pctx, pwo, out, NROWS, DD, DD);
}